// round 4
// baseline (speedup 1.0000x reference)
#include <cuda_runtime.h>
#include <math.h>

#define NN 8192
#define DDIM 200
#define NBLK 256
#define CAP (1 << 18)
#define SCAP 4096
#define KMAX 128

__device__ float g_b[NN], g_e[NN];
__device__ double g_pb[NBLK], g_pe[NBLK];
__device__ int g_Ri[NN];
__device__ float g_Rb[NN];
__device__ int g_Jj[NN];
__device__ float g_Je[NN];
__device__ unsigned long long g_keys[CAP];
__device__ unsigned g_ctr;   // zero-initialized; reset by last block each run

__device__ __forceinline__ unsigned f2u(float x) {
    unsigned u = __float_as_uint(x);
    return (u & 0x80000000u) ? ~u : (u | 0x80000000u);
}
__device__ __forceinline__ float u2f(unsigned u) {
    unsigned v = (u & 0x80000000u) ? (u & 0x7FFFFFFFu) : ~u;
    return __uint_as_float(v);
}

// one-warp bin-find over hist[256], descending rank kk_in.
#define BIN_FIND(kk_in)                                                          \
    do {                                                                         \
        unsigned lh[8];                                                          \
        int ls = 0;                                                              \
        _Pragma("unroll") for (int t = 0; t < 8; t++) {                          \
            lh[t] = hist[tid * 8 + t];                                           \
            ls += (int)lh[t];                                                    \
        }                                                                        \
        int suf = ls;                                                            \
        _Pragma("unroll") for (int o = 1; o < 32; o <<= 1) {                     \
            int u = __shfl_down_sync(0xffffffffu, suf, o);                       \
            if (tid + o < 32) suf += u;                                          \
        }                                                                        \
        int above = suf - ls;                                                    \
        int runc = above;                                                        \
        _Pragma("unroll") for (int t = 7; t >= 0; t--) {                         \
            if ((kk_in) > runc && (kk_in) <= runc + (int)lh[t]) {                \
                s_kbyte = (unsigned)(tid * 8 + t);                               \
                s_kk = (kk_in)-runc;                                             \
                s_binc = (int)lh[t];                                             \
            }                                                                    \
            runc += (int)lh[t];                                                  \
        }                                                                        \
    } while (0)

__global__ void __launch_bounds__(1024) k_fused(const float* __restrict__ G,
                                                const float* __restrict__ wb,
                                                const float* __restrict__ we,
                                                const int* __restrict__ kp,
                                                float* __restrict__ out,
                                                int out_size) {
    __shared__ __align__(16) float buf[NN];   // 32KB; later aliased as cand[]
    __shared__ float wtot[32], wexcl[32];
    __shared__ unsigned hist[256];
    __shared__ double sda[8], sdb[8];
    __shared__ double eb[32], ee[32];
    __shared__ float s_denom;
    __shared__ unsigned s_kbyte;
    __shared__ int s_kk, s_binc;
    __shared__ unsigned long long s_kth;
    __shared__ int s_nR, s_nJ, s_cnt, s_last;
    __shared__ unsigned s_m;
    __shared__ unsigned long long stop[KMAX];

    int tid = threadIdx.x;
    int lane = tid & 31;
    int wid = tid >> 5;

    // ================= Phase 0: GEMV (all blocks) =================
    {
        int row = blockIdx.x * 32 + wid;
        const float* rp = G + (size_t)row * DDIM;
        float sbv = 0.f, sev = 0.f;
#pragma unroll
        for (int t = 0; t < 7; t++) {
            int c = lane + 32 * t;
            if (c < DDIM) {
                float g = rp[c];
                sbv += g * wb[c];
                sev += g * we[c];
            }
        }
#pragma unroll
        for (int o = 16; o; o >>= 1) {
            sbv += __shfl_xor_sync(0xffffffffu, sbv, o);
            sev += __shfl_xor_sync(0xffffffffu, sev, o);
        }
        if (lane == 0) {
            g_b[row] = sbv;
            g_e[row] = sev;
            eb[wid] = (double)expf(sbv);
            ee[wid] = (double)expf(sev);
        }
    }
    __syncthreads();
    if (tid == 0) {
        double a = 0.0, b = 0.0;
#pragma unroll
        for (int w = 0; w < 32; w++) { a += eb[w]; b += ee[w]; }
        g_pb[blockIdx.x] = a;
        g_pe[blockIdx.x] = b;
    }
    __threadfence();   // make this block's global writes visible
    __syncthreads();
    if (tid == 0) {
        unsigned old = atomicAdd(&g_ctr, 1u);
        s_last = (old == (unsigned)(NBLK - 1)) ? 1 : 0;
    }
    __syncthreads();
    if (!s_last) return;
    if (tid == 0) g_ctr = 0u;   // reset for next graph replay (stream-ordered)
    __threadfence();            // acquire side before reading other blocks' data
    __syncthreads();

    // ================= Master phases (last block only) =================
    int k = *kp;
    if (k < 1) k = 1;
    if (k > KMAX) k = KMAX;
    int base = tid * 8;
    if (tid == 0) { s_nR = 0; s_nJ = 0; s_m = 0; s_cnt = 0; }

    // ---- denominator: warp reduce of 2x256 partials ----
    {
        double dv = 0.0;
        if (tid < 256) dv = g_pb[tid];
        else if (tid < 512) dv = g_pe[tid - 256];
#pragma unroll
        for (int o = 16; o; o >>= 1) dv += __shfl_down_sync(0xffffffffu, dv, o);
        if (lane == 0 && wid < 16) {
            if (wid < 8) sda[wid] = dv; else sdb[wid - 8] = dv;
        }
    }

    // ---- prefix-max(b); c_j = m_j + e_j -> buf ----
    float pl[8];
    float lex;
    {
        float run = -INFINITY;
#pragma unroll
        for (int t = 0; t < 8; t++) {
            run = fmaxf(run, g_b[base + t]);
            pl[t] = run;
        }
        float incl = run;
#pragma unroll
        for (int o = 1; o < 32; o <<= 1) {
            float u = __shfl_up_sync(0xffffffffu, incl, o);
            if (lane >= o) incl = fmaxf(incl, u);
        }
        if (lane == 31) wtot[wid] = incl;
        lex = __shfl_up_sync(0xffffffffu, incl, 1);
        if (lane == 0) lex = -INFINITY;
    }
    __syncthreads();
    if (tid < 32) {
        float incl = wtot[tid];
#pragma unroll
        for (int o = 1; o < 32; o <<= 1) {
            float u = __shfl_up_sync(0xffffffffu, incl, o);
            if (tid >= o) incl = fmaxf(incl, u);
        }
        float ex = __shfl_up_sync(0xffffffffu, incl, 1);
        if (tid == 0) ex = -INFINITY;
        wexcl[tid] = ex;
    }
    __syncthreads();
    {
        float ex = fmaxf(wexcl[wid], lex);
#pragma unroll
        for (int t = 0; t < 8; t++)
            buf[base + t] = fmaxf(pl[t], ex) + g_e[base + t];
    }
    if (tid == 0) {
        double a = 0.0, b2 = 0.0;
#pragma unroll
        for (int w = 0; w < 8; w++) { a += sda[w]; b2 += sdb[w]; }
        s_denom = (float)(a * b2);
    }
    __syncthreads();

    // ---- select-1: 3-pass radix on c (24 high bits) -> threshold T ----
    unsigned pref = 0;
    {
        int kk = k;
#pragma unroll
        for (int pass = 0; pass < 3; pass++) {
            int shift = 24 - 8 * pass;
            if (tid < 256) hist[tid] = 0u;
            __syncthreads();
#pragma unroll
            for (int it = 0; it < 8; it++) {
                int idx = tid + it * 1024;
                unsigned u = f2u(buf[idx]);
                bool ok = (pass == 0) || ((u >> (shift + 8)) == pref);
                int binx = ok ? (int)((u >> shift) & 255u) : (0x100 + lane);
                unsigned m = __match_any_sync(0xffffffffu, binx);
                if (ok && ((int)(__ffs(m) - 1) == lane))
                    atomicAdd(&hist[binx], (unsigned)__popc(m));
            }
            __syncthreads();
            if (tid < 32) BIN_FIND(kk);
            __syncthreads();
            pref = (pref << 8) | s_kbyte;
            kk = s_kk;
        }
    }
    float T = u2f(pref << 8);
    float Tr = T - (fabsf(T) * 1e-6f + 1e-6f);

    // ---- build J list (columns with c_j >= Tr) ----
#pragma unroll
    for (int it = 0; it < 8; it++) {
        int idx = tid + it * 1024;
        if (buf[idx] >= Tr) {
            int p = atomicAdd(&s_nJ, 1);
            g_Jj[p] = idx;
            g_Je[p] = g_e[idx];
        }
    }

    // ---- suffix-max(e) + build R list ----
    {
        float sl[8];
        float run = -INFINITY;
#pragma unroll
        for (int t = 7; t >= 0; t--) {
            run = fmaxf(run, g_e[base + t]);
            sl[t] = run;
        }
        float incl = run;
#pragma unroll
        for (int o = 1; o < 32; o <<= 1) {
            float u = __shfl_down_sync(0xffffffffu, incl, o);
            if (lane + o < 32) incl = fmaxf(incl, u);
        }
        if (lane == 0) wtot[wid] = incl;
        float lex2 = __shfl_down_sync(0xffffffffu, incl, 1);
        if (lane == 31) lex2 = -INFINITY;
        __syncthreads();
        if (tid < 32) {
            float incl2 = wtot[tid];
#pragma unroll
            for (int o = 1; o < 32; o <<= 1) {
                float u = __shfl_down_sync(0xffffffffu, incl2, o);
                if (tid + o < 32) incl2 = fmaxf(incl2, u);
            }
            float ex = __shfl_down_sync(0xffffffffu, incl2, 1);
            if (tid == 31) ex = -INFINITY;
            wexcl[tid] = ex;
        }
        __syncthreads();
        float ex = fmaxf(wexcl[wid], lex2);
#pragma unroll
        for (int t = 0; t < 8; t++) {
            float smax = fmaxf(sl[t], ex);
            int i = base + t;
            float bi = g_b[i];
            if (bi + smax >= Tr) {
                int p = atomicAdd(&s_nR, 1);
                g_Ri[p] = i;
                g_Rb[p] = bi;
            }
        }
    }
    __syncthreads();   // buf now dead -> reuse as candidate key storage
    unsigned long long* cand = reinterpret_cast<unsigned long long*>(buf);

    // ---- enumerate R x J (warp per row); keys to smem (global fallback) ----
    {
        int nR = s_nR, nJ = s_nJ;
        for (int r = wid; r < nR; r += 32) {
            int i = g_Ri[r];
            float bi = g_Rb[r];
            float t2 = Tr - bi;
            for (int q = lane; q < nJ; q += 32) {
                int j = g_Jj[q];
                float ej = g_Je[q];
                if (j >= i && ej >= t2) {
                    float v = expf(bi + ej);
                    unsigned fl = (unsigned)i * NN + (unsigned)j;
                    unsigned long long key =
                        ((unsigned long long)__float_as_uint(v) << 32) |
                        (unsigned long long)(0xFFFFFFFFu - fl);
                    unsigned p = atomicAdd(&s_m, 1u);
                    if (p < SCAP) cand[p] = key;
                    if (p < CAP) g_keys[p] = key;
                }
            }
        }
    }
    __syncthreads();
    unsigned M = s_m;
    if (M > (unsigned)CAP) M = (unsigned)CAP;
    bool insm = (M <= (unsigned)SCAP);

    // ---- select-2: radix on 64-bit keys, early exit (keys distinct) ----
    {
        unsigned long long pref64 = 0ull;
        int kk = k;
        int fshift = 0;
        for (int pass = 0; pass < 8; pass++) {
            int shift = 56 - 8 * pass;
            if (tid < 256) hist[tid] = 0u;
            __syncthreads();
            for (unsigned c = tid; c < M; c += 1024) {
                unsigned long long key = insm ? cand[c] : g_keys[c];
                bool ok = (pass == 0) || ((key >> (shift + 8)) == pref64);
                unsigned act = __activemask();
                int binx = ok ? (int)((key >> shift) & 255ull) : (0x100 + lane);
                unsigned m = __match_any_sync(act, binx);
                if (ok && ((int)(__ffs(m) - 1) == lane))
                    atomicAdd(&hist[binx], (unsigned)__popc(m));
            }
            __syncthreads();
            if (tid < 32) BIN_FIND(kk);
            __syncthreads();
            pref64 = (pref64 << 8) | (unsigned long long)s_kbyte;
            kk = s_kk;
            fshift = shift;
            if (s_binc == 1) break;
            __syncthreads();
        }
        for (unsigned c = tid; c < M; c += 1024) {
            unsigned long long key = insm ? cand[c] : g_keys[c];
            if ((key >> fshift) == pref64) s_kth = key;
        }
    }
    __syncthreads();

    // ---- gather exactly k winners (all keys distinct) ----
    {
        unsigned long long kth = s_kth;
        for (unsigned c = tid; c < M; c += 1024) {
            unsigned long long key = insm ? cand[c] : g_keys[c];
            if (key >= kth) {
                int p = atomicAdd(&s_cnt, 1);
                if (p < KMAX) stop[p] = key;
            }
        }
    }
    __syncthreads();
    int kv = s_cnt;
    if (kv > k) kv = k;
    if (kv > KMAX) kv = KMAX;

    // ---- rank sort (O(k^2)) + output ----
    float denom = s_denom;
    if (tid < kv) {
        unsigned long long mykey = stop[tid];
        int rank = 0;
        for (int u = 0; u < kv; u++) rank += (stop[u] > mykey);
        if (rank < k) {
            unsigned fl = 0xFFFFFFFFu - (unsigned)(mykey & 0xFFFFFFFFull);
            unsigned ii = fl / NN, jj = fl % NN;
            float v = __uint_as_float((unsigned)(mykey >> 32));
            if (2 * rank + 1 < out_size) {
                out[2 * rank] = (float)ii;
                out[2 * rank + 1] = (float)jj;
            }
            if (2 * k + rank < out_size) out[2 * k + rank] = v / denom;
        }
    }
    for (int c = 3 * k + tid; c < out_size; c += 1024) out[c] = 0.f;
}

extern "C" void kernel_launch(void* const* d_in, const int* in_sizes, int n_in,
                              void* d_out, int out_size) {
    const float* G = (const float*)d_in[0];
    const float* wb = (const float*)d_in[1];
    const float* we = (const float*)d_in[2];
    const int* kp = (const int*)d_in[3];
    float* out = (float*)d_out;

    k_fused<<<NBLK, 1024>>>(G, wb, we, kp, out, out_size);
}

// round 5
// speedup vs baseline: 1.1304x; 1.1304x over previous
#include <cuda_runtime.h>
#include <math.h>

#define NN 8192
#define DDIM 200
#define NB 256
#define CAP (1 << 18)
#define SCAP 4096
#define JCAP 1536
#define KMAX 128

__device__ float g_b[NN], g_e[NN];
__device__ double g_pb[NB], g_pe[NB];
__device__ int g_Ri[NN];
__device__ float g_Rb[NN];
__device__ int g_Jj[NN];
__device__ float g_Je[NN];
__device__ unsigned long long g_keys[CAP];

// ---------- GEMV: warp per row, float4 ----------
__global__ void __launch_bounds__(1024) k_dots(const float* __restrict__ G,
                                               const float* __restrict__ wb,
                                               const float* __restrict__ we) {
    int wib = threadIdx.x >> 5;
    int lane = threadIdx.x & 31;
    int row = blockIdx.x * 32 + wib;
    const float4* rp = reinterpret_cast<const float4*>(G + (size_t)row * DDIM);
    const float4* wb4 = reinterpret_cast<const float4*>(wb);
    const float4* we4 = reinterpret_cast<const float4*>(we);
    float sbv = 0.f, sev = 0.f;
#pragma unroll
    for (int t = 0; t < 2; t++) {
        int q = lane + 32 * t;
        if (q < DDIM / 4) {
            float4 g = rp[q];
            float4 b4 = __ldg(&wb4[q]);
            float4 e4 = __ldg(&we4[q]);
            sbv = fmaf(g.x, b4.x, fmaf(g.y, b4.y, fmaf(g.z, b4.z, fmaf(g.w, b4.w, sbv))));
            sev = fmaf(g.x, e4.x, fmaf(g.y, e4.y, fmaf(g.z, e4.z, fmaf(g.w, e4.w, sev))));
        }
    }
#pragma unroll
    for (int o = 16; o; o >>= 1) {
        sbv += __shfl_xor_sync(0xffffffffu, sbv, o);
        sev += __shfl_xor_sync(0xffffffffu, sev, o);
    }
    __shared__ double eb[32], ee[32];
    if (lane == 0) {
        g_b[row] = sbv;
        g_e[row] = sev;
        eb[wib] = (double)expf(sbv);
        ee[wib] = (double)expf(sev);
    }
    __syncthreads();
    if (threadIdx.x == 0) {
        double a = 0.0, b = 0.0;
#pragma unroll
        for (int w = 0; w < 32; w++) { a += eb[w]; b += ee[w]; }
        g_pb[blockIdx.x] = a;
        g_pe[blockIdx.x] = b;
    }
}

__device__ __forceinline__ unsigned f2u(float x) {
    unsigned u = __float_as_uint(x);
    return (u & 0x80000000u) ? ~u : (u | 0x80000000u);
}
__device__ __forceinline__ float u2f(unsigned u) {
    unsigned v = (u & 0x80000000u) ? (u & 0x7FFFFFFFu) : ~u;
    return __uint_as_float(v);
}

#define BIN_FIND(kk_in)                                                          \
    do {                                                                         \
        unsigned lh[8];                                                          \
        int ls = 0;                                                              \
        _Pragma("unroll") for (int t = 0; t < 8; t++) {                          \
            lh[t] = hist[tid * 8 + t];                                           \
            ls += (int)lh[t];                                                    \
        }                                                                        \
        int suf = ls;                                                            \
        _Pragma("unroll") for (int o = 1; o < 32; o <<= 1) {                     \
            int u = __shfl_down_sync(0xffffffffu, suf, o);                       \
            if (tid + o < 32) suf += u;                                          \
        }                                                                        \
        int above = suf - ls;                                                    \
        int runc = above;                                                        \
        _Pragma("unroll") for (int t = 7; t >= 0; t--) {                         \
            if ((kk_in) > runc && (kk_in) <= runc + (int)lh[t]) {                \
                s_kbyte = (unsigned)(tid * 8 + t);                               \
                s_kk = (kk_in)-runc;                                             \
                s_binc = (int)lh[t];                                             \
            }                                                                    \
            runc += (int)lh[t];                                                  \
        }                                                                        \
    } while (0)

__global__ void __launch_bounds__(1024) k_master(const int* __restrict__ kp,
                                                 float* __restrict__ out,
                                                 int out_size) {
    __shared__ __align__(16) float buf[NN];   // 32KB; later aliased as cand[]
    __shared__ int sjidx[JCAP];               // 6KB
    __shared__ float sje[JCAP];               // 6KB
    __shared__ float wtot[32], wexcl[32];
    __shared__ unsigned hist[256];
    __shared__ double sda[8], sdb[8];
    __shared__ float s_denom;
    __shared__ unsigned s_kbyte;
    __shared__ int s_kk, s_binc;
    __shared__ unsigned long long s_kth;
    __shared__ int s_nR, s_nJ, s_cnt;
    __shared__ unsigned s_m;
    __shared__ unsigned long long stop[KMAX];

    int tid = threadIdx.x;
    int lane = tid & 31;
    int wid = tid >> 5;
    int k = *kp;
    if (k < 1) k = 1;
    if (k > KMAX) k = KMAX;
    int base = tid * 8;

    if (tid == 0) { s_nR = 0; s_nJ = 0; s_m = 0; s_cnt = 0; }

    // ---- denominator ----
    {
        double dv = 0.0;
        if (tid < 256) dv = g_pb[tid];
        else if (tid < 512) dv = g_pe[tid - 256];
#pragma unroll
        for (int o = 16; o; o >>= 1) dv += __shfl_down_sync(0xffffffffu, dv, o);
        if (lane == 0 && wid < 16) {
            if (wid < 8) sda[wid] = dv; else sdb[wid - 8] = dv;
        }
    }

    // ---- prefix-max(b); c_j = m_j + e_j -> buf ----
    float pl[8];
    float lex;
    {
        float run = -INFINITY;
#pragma unroll
        for (int t = 0; t < 8; t++) {
            run = fmaxf(run, g_b[base + t]);
            pl[t] = run;
        }
        float incl = run;
#pragma unroll
        for (int o = 1; o < 32; o <<= 1) {
            float u = __shfl_up_sync(0xffffffffu, incl, o);
            if (lane >= o) incl = fmaxf(incl, u);
        }
        if (lane == 31) wtot[wid] = incl;
        lex = __shfl_up_sync(0xffffffffu, incl, 1);
        if (lane == 0) lex = -INFINITY;
    }
    __syncthreads();
    if (tid < 32) {
        float incl = wtot[tid];
#pragma unroll
        for (int o = 1; o < 32; o <<= 1) {
            float u = __shfl_up_sync(0xffffffffu, incl, o);
            if (tid >= o) incl = fmaxf(incl, u);
        }
        float ex = __shfl_up_sync(0xffffffffu, incl, 1);
        if (tid == 0) ex = -INFINITY;
        wexcl[tid] = ex;
    }
    __syncthreads();
    {
        float ex = fmaxf(wexcl[wid], lex);
#pragma unroll
        for (int t = 0; t < 8; t++)
            buf[base + t] = fmaxf(pl[t], ex) + g_e[base + t];
    }
    if (tid == 0) {
        double a = 0.0, b2 = 0.0;
#pragma unroll
        for (int w = 0; w < 8; w++) { a += sda[w]; b2 += sdb[w]; }
        s_denom = (float)(a * b2);
    }
    __syncthreads();

    // ---- select-1: 3-pass radix (24 high bits) -> threshold T ----
    unsigned pref = 0;
    {
        int kk = k;
#pragma unroll
        for (int pass = 0; pass < 3; pass++) {
            int shift = 24 - 8 * pass;
            if (tid < 256) hist[tid] = 0u;
            __syncthreads();
#pragma unroll
            for (int it = 0; it < 8; it++) {
                int idx = tid + it * 1024;
                unsigned u = f2u(buf[idx]);
                bool ok = (pass == 0) || ((u >> (shift + 8)) == pref);
                int binx = ok ? (int)((u >> shift) & 255u) : (0x100 + lane);
                unsigned m = __match_any_sync(0xffffffffu, binx);
                if (ok && ((int)(__ffs(m) - 1) == lane))
                    atomicAdd(&hist[binx], (unsigned)__popc(m));
            }
            __syncthreads();
            if (tid < 32) BIN_FIND(kk);
            __syncthreads();
            pref = (pref << 8) | s_kbyte;
            kk = s_kk;
        }
    }
    float T = u2f(pref << 8);
    float Tr = T - (fabsf(T) * 1e-6f + 1e-6f);

    // ---- build J list (smem with global fallback) ----
#pragma unroll
    for (int it = 0; it < 8; it++) {
        int idx = tid + it * 1024;
        if (buf[idx] >= Tr) {
            float ej = g_e[idx];
            int p = atomicAdd(&s_nJ, 1);
            if (p < JCAP) { sjidx[p] = idx; sje[p] = ej; }
            g_Jj[p] = idx;
            g_Je[p] = ej;
        }
    }

    // ---- suffix-max(e) + R list ----
    {
        float sl[8];
        float run = -INFINITY;
#pragma unroll
        for (int t = 7; t >= 0; t--) {
            run = fmaxf(run, g_e[base + t]);
            sl[t] = run;
        }
        float incl = run;
#pragma unroll
        for (int o = 1; o < 32; o <<= 1) {
            float u = __shfl_down_sync(0xffffffffu, incl, o);
            if (lane + o < 32) incl = fmaxf(incl, u);
        }
        if (lane == 0) wtot[wid] = incl;
        float lex2 = __shfl_down_sync(0xffffffffu, incl, 1);
        if (lane == 31) lex2 = -INFINITY;
        __syncthreads();
        if (tid < 32) {
            float incl2 = wtot[tid];
#pragma unroll
            for (int o = 1; o < 32; o <<= 1) {
                float u = __shfl_down_sync(0xffffffffu, incl2, o);
                if (tid + o < 32) incl2 = fmaxf(incl2, u);
            }
            float ex = __shfl_down_sync(0xffffffffu, incl2, 1);
            if (tid == 31) ex = -INFINITY;
            wexcl[tid] = ex;
        }
        __syncthreads();
        float ex = fmaxf(wexcl[wid], lex2);
#pragma unroll
        for (int t = 0; t < 8; t++) {
            float smax = fmaxf(sl[t], ex);
            int i = base + t;
            float bi = g_b[i];
            if (bi + smax >= Tr) {
                int p = atomicAdd(&s_nR, 1);
                g_Ri[p] = i;
                g_Rb[p] = bi;
            }
        }
    }
    __syncthreads();   // buf dead -> candidate keys
    unsigned long long* cand = reinterpret_cast<unsigned long long*>(buf);

    // ---- enumerate R x J (warp per row); keys to smem (global fallback) ----
    {
        int nR = s_nR, nJ = s_nJ;
        for (int r = wid; r < nR; r += 32) {
            int i = g_Ri[r];
            float bi = g_Rb[r];
            float t2 = Tr - bi;
            for (int q = lane; q < nJ; q += 32) {
                int j;
                float ej;
                if (q < JCAP) { j = sjidx[q]; ej = sje[q]; }
                else { j = g_Jj[q]; ej = g_Je[q]; }
                if (j >= i && ej >= t2) {
                    float v = expf(bi + ej);
                    unsigned fl = (unsigned)i * NN + (unsigned)j;
                    unsigned long long key =
                        ((unsigned long long)__float_as_uint(v) << 32) |
                        (unsigned long long)(0xFFFFFFFFu - fl);
                    unsigned p = atomicAdd(&s_m, 1u);
                    if (p < SCAP) cand[p] = key;
                    else if (p < CAP) g_keys[p] = key;
                }
            }
        }
    }
    __syncthreads();
    unsigned M = s_m;
    if (M > (unsigned)CAP) M = (unsigned)CAP;
    bool insm = (M <= (unsigned)SCAP);

    // ---- select-2: radix on 64-bit keys, early exit (keys distinct) ----
    {
        unsigned long long pref64 = 0ull;
        int kk = k;
        int fshift = 0;
        for (int pass = 0; pass < 8; pass++) {
            int shift = 56 - 8 * pass;
            if (tid < 256) hist[tid] = 0u;
            __syncthreads();
            for (unsigned c = tid; c < M; c += 1024) {
                unsigned long long key =
                    (insm || c < SCAP) ? cand[c] : g_keys[c];
                bool ok = (pass == 0) || ((key >> (shift + 8)) == pref64);
                unsigned act = __activemask();
                int binx = ok ? (int)((key >> shift) & 255ull) : (0x100 + lane);
                unsigned m = __match_any_sync(act, binx);
                if (ok && ((int)(__ffs(m) - 1) == lane))
                    atomicAdd(&hist[binx], (unsigned)__popc(m));
            }
            __syncthreads();
            if (tid < 32) BIN_FIND(kk);
            __syncthreads();
            pref64 = (pref64 << 8) | (unsigned long long)s_kbyte;
            kk = s_kk;
            fshift = shift;
            if (s_binc == 1) break;
            __syncthreads();
        }
        for (unsigned c = tid; c < M; c += 1024) {
            unsigned long long key = (insm || c < SCAP) ? cand[c] : g_keys[c];
            if ((key >> fshift) == pref64) s_kth = key;
        }
    }
    __syncthreads();

    // ---- gather exactly k winners ----
    {
        unsigned long long kth = s_kth;
        for (unsigned c = tid; c < M; c += 1024) {
            unsigned long long key = (insm || c < SCAP) ? cand[c] : g_keys[c];
            if (key >= kth) {
                int p = atomicAdd(&s_cnt, 1);
                if (p < KMAX) stop[p] = key;
            }
        }
    }
    __syncthreads();
    int kv = s_cnt;
    if (kv > k) kv = k;
    if (kv > KMAX) kv = KMAX;

    // ---- rank sort + output ----
    float denom = s_denom;
    if (tid < kv) {
        unsigned long long mykey = stop[tid];
        int rank = 0;
        for (int u = 0; u < kv; u++) rank += (stop[u] > mykey);
        if (rank < k) {
            unsigned fl = 0xFFFFFFFFu - (unsigned)(mykey & 0xFFFFFFFFull);
            unsigned ii = fl / NN, jj = fl % NN;
            float v = __uint_as_float((unsigned)(mykey >> 32));
            if (2 * rank + 1 < out_size) {
                out[2 * rank] = (float)ii;
                out[2 * rank + 1] = (float)jj;
            }
            if (2 * k + rank < out_size) out[2 * k + rank] = v / denom;
        }
    }
    for (int c = 3 * k + tid; c < out_size; c += 1024) out[c] = 0.f;
}

extern "C" void kernel_launch(void* const* d_in, const int* in_sizes, int n_in,
                              void* d_out, int out_size) {
    const float* G = (const float*)d_in[0];
    const float* wb = (const float*)d_in[1];
    const float* we = (const float*)d_in[2];
    const int* kp = (const int*)d_in[3];
    float* out = (float*)d_out;

    k_dots<<<NB, 1024>>>(G, wb, we);
    k_master<<<1, 1024>>>(kp, out, out_size);
}

// round 6
// speedup vs baseline: 1.1498x; 1.0172x over previous
#include <cuda_runtime.h>
#include <math.h>

#define NN 8192
#define DDIM 200
#define NBD 128
#define GCAP (1 << 18)
#define SCAP 4096
#define JCAP 1024
#define RCAP 256
#define KMAX 128

__device__ float g_b[NN], g_e[NN];
__device__ double g_pb[NBD], g_pe[NBD];
__device__ int g_Ri[NN];
__device__ float g_Rb[NN];
__device__ int g_Jj[NN];
__device__ float g_Je[NN];
__device__ unsigned long long g_keys[GCAP];

// ---------- GEMV: 128 blocks (single wave), 2 rows per warp ----------
__global__ void __launch_bounds__(1024) k_dots(const float* __restrict__ G,
                                               const float* __restrict__ wb,
                                               const float* __restrict__ we) {
    int wib = threadIdx.x >> 5;
    int lane = threadIdx.x & 31;
    int row0 = blockIdx.x * 64 + wib * 2;
    const float4* wb4 = reinterpret_cast<const float4*>(wb);
    const float4* we4 = reinterpret_cast<const float4*>(we);
    double accb = 0.0, acce = 0.0;
#pragma unroll
    for (int r = 0; r < 2; r++) {
        int row = row0 + r;
        const float4* rp = reinterpret_cast<const float4*>(G + (size_t)row * DDIM);
        float sb = 0.f, se = 0.f;
#pragma unroll
        for (int t = 0; t < 2; t++) {
            int q = lane + 32 * t;
            if (q < DDIM / 4) {
                float4 g = rp[q];
                float4 b4 = __ldg(&wb4[q]);
                float4 e4 = __ldg(&we4[q]);
                sb = fmaf(g.x, b4.x, fmaf(g.y, b4.y, fmaf(g.z, b4.z, fmaf(g.w, b4.w, sb))));
                se = fmaf(g.x, e4.x, fmaf(g.y, e4.y, fmaf(g.z, e4.z, fmaf(g.w, e4.w, se))));
            }
        }
#pragma unroll
        for (int o = 16; o; o >>= 1) {
            sb += __shfl_xor_sync(0xffffffffu, sb, o);
            se += __shfl_xor_sync(0xffffffffu, se, o);
        }
        if (lane == 0) {
            g_b[row] = sb;
            g_e[row] = se;
            accb += (double)expf(sb);
            acce += (double)expf(se);
        }
    }
    __shared__ double eb[32], ee[32];
    if (lane == 0) { eb[wib] = accb; ee[wib] = acce; }
    __syncthreads();
    if (threadIdx.x == 0) {
        double a = 0.0, b = 0.0;
#pragma unroll
        for (int w = 0; w < 32; w++) { a += eb[w]; b += ee[w]; }
        g_pb[blockIdx.x] = a;
        g_pe[blockIdx.x] = b;
    }
}

__device__ __forceinline__ unsigned f2u(float x) {
    unsigned u = __float_as_uint(x);
    return (u & 0x80000000u) ? ~u : (u | 0x80000000u);
}
__device__ __forceinline__ float u2f(unsigned u) {
    unsigned v = (u & 0x80000000u) ? (u & 0x7FFFFFFFu) : ~u;
    return __uint_as_float(v);
}

// one-warp bin-find over H[256], descending rank kk_in (call with tid<32)
#define BIN_FIND(H, kk_in)                                                       \
    do {                                                                         \
        unsigned lh[8];                                                          \
        int ls = 0;                                                              \
        _Pragma("unroll") for (int t = 0; t < 8; t++) {                          \
            lh[t] = (H)[tid * 8 + t];                                            \
            ls += (int)lh[t];                                                    \
        }                                                                        \
        int suf = ls;                                                            \
        _Pragma("unroll") for (int o = 1; o < 32; o <<= 1) {                     \
            int u = __shfl_down_sync(0xffffffffu, suf, o);                       \
            if (tid + o < 32) suf += u;                                          \
        }                                                                        \
        int above = suf - ls;                                                    \
        int runc = above;                                                        \
        _Pragma("unroll") for (int t = 7; t >= 0; t--) {                         \
            if ((kk_in) > runc && (kk_in) <= runc + (int)lh[t]) {                \
                s_kbyte = (unsigned)(tid * 8 + t);                               \
                s_kk = (kk_in)-runc;                                             \
                s_binc = (int)lh[t];                                             \
            }                                                                    \
            runc += (int)lh[t];                                                  \
        }                                                                        \
    } while (0)

__global__ void __launch_bounds__(1024) k_master(const int* __restrict__ kp,
                                                 float* __restrict__ out,
                                                 int out_size) {
    __shared__ __align__(16) unsigned long long cand[SCAP];  // 32KB
    __shared__ int sjidx[JCAP];
    __shared__ float sje[JCAP];                              // 8KB
    __shared__ int sri[RCAP];
    __shared__ float srb[RCAP];                              // 2KB
    __shared__ float wtot[32], wexcl[32], stot[32], sexcl[32];
    __shared__ unsigned histA[256], histB[256];
    __shared__ double sda[4], sdb[4];
    __shared__ float s_denom;
    __shared__ unsigned s_kbyte;
    __shared__ int s_kk, s_binc;
    __shared__ unsigned long long s_kth, s_kmin, s_kmax;
    __shared__ int s_nR, s_nJ, s_cnt;
    __shared__ unsigned s_m;
    __shared__ unsigned long long stop[KMAX];

    int tid = threadIdx.x;
    int lane = tid & 31;
    int wid = tid >> 5;
    int k = *kp;
    if (k < 1) k = 1;
    if (k > KMAX) k = KMAX;
    int base = tid * 8;

    // ---- load working set once into registers ----
    float bi[8], el[8], sl[8], cl[8];
#pragma unroll
    for (int t = 0; t < 8; t++) bi[t] = g_b[base + t];
#pragma unroll
    for (int t = 0; t < 8; t++) el[t] = g_e[base + t];

    // local prefix-max(b) -> cl (partial); local suffix-max(e) -> sl (partial)
    float lex, lex2;
    {
        float run = -INFINITY;
#pragma unroll
        for (int t = 0; t < 8; t++) { run = fmaxf(run, bi[t]); cl[t] = run; }
        float incl = run;
#pragma unroll
        for (int o = 1; o < 32; o <<= 1) {
            float u = __shfl_up_sync(0xffffffffu, incl, o);
            if (lane >= o) incl = fmaxf(incl, u);
        }
        if (lane == 31) wtot[wid] = incl;
        lex = __shfl_up_sync(0xffffffffu, incl, 1);
        if (lane == 0) lex = -INFINITY;
    }
    {
        float run = -INFINITY;
#pragma unroll
        for (int t = 7; t >= 0; t--) { run = fmaxf(run, el[t]); sl[t] = run; }
        float incl = run;
#pragma unroll
        for (int o = 1; o < 32; o <<= 1) {
            float u = __shfl_down_sync(0xffffffffu, incl, o);
            if (lane + o < 32) incl = fmaxf(incl, u);
        }
        if (lane == 0) stot[wid] = incl;
        lex2 = __shfl_down_sync(0xffffffffu, incl, 1);
        if (lane == 31) lex2 = -INFINITY;
    }
    // denominator partial reduce (warps 0-7, concurrent with above in schedule)
    if (wid < 8) {
        double dv = (tid < 128) ? g_pb[tid] : g_pe[tid - 128];
#pragma unroll
        for (int o = 16; o; o >>= 1) dv += __shfl_down_sync(0xffffffffu, dv, o);
        if (lane == 0) { if (wid < 4) sda[wid] = dv; else sdb[wid - 4] = dv; }
    }
    // hist clears + scalar init (free lanes)
    if (tid >= 512 && tid < 768) histA[tid - 512] = 0u;
    if (tid >= 768) histB[tid - 768] = 0u;
    if (tid == 0) { s_nR = 0; s_nJ = 0; s_m = 0; s_cnt = 0; s_kmin = ~0ull; s_kmax = 0ull; }
    __syncthreads();  // bar1

    if (wid == 0) {  // cross-warp prefix scan
        float incl = wtot[lane];
#pragma unroll
        for (int o = 1; o < 32; o <<= 1) {
            float u = __shfl_up_sync(0xffffffffu, incl, o);
            if (lane >= o) incl = fmaxf(incl, u);
        }
        float ex = __shfl_up_sync(0xffffffffu, incl, 1);
        if (lane == 0) ex = -INFINITY;
        wexcl[lane] = ex;
    } else if (wid == 1) {  // cross-warp suffix scan
        float incl = stot[lane];
#pragma unroll
        for (int o = 1; o < 32; o <<= 1) {
            float u = __shfl_down_sync(0xffffffffu, incl, o);
            if (lane + o < 32) incl = fmaxf(incl, u);
        }
        float ex = __shfl_down_sync(0xffffffffu, incl, 1);
        if (lane == 31) ex = -INFINITY;
        sexcl[lane] = ex;
    } else if (tid == 64) {
        double a = sda[0] + sda[1] + sda[2] + sda[3];
        double b2 = sdb[0] + sdb[1] + sdb[2] + sdb[3];
        s_denom = (float)(a * b2);
    }
    __syncthreads();  // bar2

    {
        float exP = fmaxf(wexcl[wid], lex);
        float exS = fmaxf(sexcl[wid], lex2);
#pragma unroll
        for (int t = 0; t < 8; t++) cl[t] = fmaxf(cl[t], exP) + el[t];
#pragma unroll
        for (int t = 0; t < 8; t++) sl[t] = fmaxf(sl[t], exS);
    }

    // ---- select-1: 3-pass radix on cl (registers), ping-pong hists ----
    unsigned pref;
    {
        // pass 0 (shift 24) -> histA
#pragma unroll
        for (int t = 0; t < 8; t++) {
            unsigned u = f2u(cl[t]);
            int binx = (int)(u >> 24);
            unsigned m = __match_any_sync(0xffffffffu, binx);
            if ((int)(__ffs(m) - 1) == lane) atomicAdd(&histA[binx], (unsigned)__popc(m));
        }
        __syncthreads();  // bar3
        if (wid == 0) BIN_FIND(histA, k);
        __syncthreads();  // bar4
        pref = s_kbyte;
        int kk = s_kk;
        // pass 1 (shift 16) -> histB
#pragma unroll
        for (int t = 0; t < 8; t++) {
            unsigned u = f2u(cl[t]);
            bool ok = ((u >> 24) == pref);
            int binx = ok ? (int)((u >> 16) & 255u) : (0x100 + lane);
            unsigned m = __match_any_sync(0xffffffffu, binx);
            if (ok && ((int)(__ffs(m) - 1) == lane)) atomicAdd(&histB[binx], (unsigned)__popc(m));
        }
        __syncthreads();  // bar5
        if (wid == 0) BIN_FIND(histB, kk);
        else if (tid >= 512 && tid < 768) histA[tid - 512] = 0u;  // clear A for pass2
        __syncthreads();  // bar6
        pref = (pref << 8) | s_kbyte;
        kk = s_kk;
        // pass 2 (shift 8) -> histA
#pragma unroll
        for (int t = 0; t < 8; t++) {
            unsigned u = f2u(cl[t]);
            bool ok = ((u >> 16) == pref);
            int binx = ok ? (int)((u >> 8) & 255u) : (0x100 + lane);
            unsigned m = __match_any_sync(0xffffffffu, binx);
            if (ok && ((int)(__ffs(m) - 1) == lane)) atomicAdd(&histA[binx], (unsigned)__popc(m));
        }
        __syncthreads();  // bar7
        if (wid == 0) BIN_FIND(histA, kk);
        else if (tid >= 512 && tid < 768) histA[tid - 512 /*dummy keep*/] += 0u;
        __syncthreads();  // bar8
        pref = (pref << 8) | s_kbyte;
    }
    float T = u2f(pref << 8);
    float Tr = T - (fabsf(T) * 1e-6f + 1e-6f);

    // ---- build J and R lists from registers ----
#pragma unroll
    for (int t = 0; t < 8; t++) {
        if (cl[t] >= Tr) {
            int p = atomicAdd(&s_nJ, 1);
            if (p < JCAP) { sjidx[p] = base + t; sje[p] = el[t]; }
            else { g_Jj[p] = base + t; g_Je[p] = el[t]; }
        }
    }
#pragma unroll
    for (int t = 0; t < 8; t++) {
        if (bi[t] + sl[t] >= Tr) {
            int p = atomicAdd(&s_nR, 1);
            if (p < RCAP) { sri[p] = base + t; srb[p] = bi[t]; }
            else { g_Ri[p] = base + t; g_Rb[p] = bi[t]; }
        }
    }
    // clear both hists for select-2 while others do atomics
    if (tid >= 512 && tid < 768) histA[tid - 512] = 0u;
    if (tid >= 768) histB[tid - 768] = 0u;
    __syncthreads();  // bar9

    // ---- enumerate R x J (warp per row); kmin/kmax tracked inline ----
    {
        int nR = s_nR, nJ = s_nJ;
        for (int r = wid; r < nR; r += 32) {
            int i = (r < RCAP) ? sri[r] : g_Ri[r];
            float bv = (r < RCAP) ? srb[r] : g_Rb[r];
            float t2 = Tr - bv;
            for (int q = lane; q < nJ; q += 32) {
                int j;
                float ej;
                if (q < JCAP) { j = sjidx[q]; ej = sje[q]; }
                else { j = g_Jj[q]; ej = g_Je[q]; }
                if (j >= i && ej >= t2) {
                    float v = expf(bv + ej);
                    unsigned fl = (unsigned)i * NN + (unsigned)j;
                    unsigned long long key =
                        ((unsigned long long)__float_as_uint(v) << 32) |
                        (unsigned long long)(0xFFFFFFFFu - fl);
                    unsigned p = atomicAdd(&s_m, 1u);
                    if (p < SCAP) cand[p] = key;
                    else if (p < GCAP) g_keys[p] = key;
                    atomicMax(&s_kmax, key);
                    atomicMin(&s_kmin, key);
                }
            }
        }
    }
    __syncthreads();  // bar10
    unsigned M = s_m;
    if (M > (unsigned)GCAP) M = (unsigned)GCAP;
    unsigned long long kmin = s_kmin, kmax = s_kmax;
    unsigned long long kth;

    if (M <= (unsigned)k || kmin == kmax) {
        kth = kmin;
    } else {
        // ---- select-2: radix from first differing byte, ping-pong, early exit ----
        unsigned long long diff = kmin ^ kmax;
        int hb = 63 - __clzll(diff);
        int sshift = (hb >> 3) << 3;
        unsigned long long pref64 = (sshift == 56) ? 0ull : (kmin >> (sshift + 8));
        int kk2 = k;
        int fshift = sshift;
        int useA = 1;
        for (int shift = sshift; shift >= 0; shift -= 8) {
            unsigned* H = useA ? histA : histB;
            for (unsigned c = tid; c < M; c += 1024) {
                unsigned long long key = (c < SCAP) ? cand[c] : g_keys[c];
                bool ok = (shift == 56) || ((key >> (shift + 8)) == pref64);
                unsigned act = __activemask();
                int binx = ok ? (int)((key >> shift) & 255ull) : (0x100 + lane);
                unsigned m2 = __match_any_sync(act, binx);
                if (ok && ((int)(__ffs(m2) - 1) == lane)) atomicAdd(&H[binx], (unsigned)__popc(m2));
            }
            __syncthreads();
            if (wid == 0) BIN_FIND(H, kk2);
            else if (tid >= 512 && tid < 768) (useA ? histB : histA)[tid - 512] = 0u;
            __syncthreads();
            pref64 = (pref64 << 8) | (unsigned long long)s_kbyte;
            kk2 = s_kk;
            fshift = shift;
            useA ^= 1;
            if (s_binc == 1) break;
        }
        // retrieve the unique k-th key
        for (unsigned c = tid; c < M; c += 1024) {
            unsigned long long key = (c < SCAP) ? cand[c] : g_keys[c];
            if ((key >> fshift) == pref64) s_kth = key;
        }
        __syncthreads();
        kth = s_kth;
    }

    // ---- gather exactly k winners (keys distinct) ----
    for (unsigned c = tid; c < M; c += 1024) {
        unsigned long long key = (c < SCAP) ? cand[c] : g_keys[c];
        if (key >= kth) {
            int p = atomicAdd(&s_cnt, 1);
            if (p < KMAX) stop[p] = key;
        }
    }
    __syncthreads();
    int kv = s_cnt;
    if (kv > k) kv = k;
    if (kv > KMAX) kv = KMAX;

    // ---- rank sort + output ----
    float denom = s_denom;
    if (tid < kv) {
        unsigned long long mykey = stop[tid];
        int rank = 0;
        for (int u = 0; u < kv; u++) rank += (stop[u] > mykey);
        if (rank < k) {
            unsigned fl = 0xFFFFFFFFu - (unsigned)(mykey & 0xFFFFFFFFull);
            unsigned ii = fl / NN, jj = fl % NN;
            float v = __uint_as_float((unsigned)(mykey >> 32));
            if (2 * rank + 1 < out_size) {
                out[2 * rank] = (float)ii;
                out[2 * rank + 1] = (float)jj;
            }
            if (2 * k + rank < out_size) out[2 * k + rank] = v / denom;
        }
    }
    for (int c = 3 * k + tid; c < out_size; c += 1024) out[c] = 0.f;
}

extern "C" void kernel_launch(void* const* d_in, const int* in_sizes, int n_in,
                              void* d_out, int out_size) {
    const float* G = (const float*)d_in[0];
    const float* wb = (const float*)d_in[1];
    const float* we = (const float*)d_in[2];
    const int* kp = (const int*)d_in[3];
    float* out = (float*)d_out;

    k_dots<<<NBD, 1024>>>(G, wb, we);
    k_master<<<1, 1024>>>(kp, out, out_size);
}

// round 8
// speedup vs baseline: 1.2740x; 1.1080x over previous
#include <cuda_runtime.h>
#include <math.h>

#define NN 8192
#define DDIM 200
#define NBD 256
#define GCAP (1 << 18)
#define SCAP 3072
#define JCAP 1024
#define RCAP 256
#define GATH 512
#define NBIN 2048
#define KMAX 128

__device__ float g_b[NN], g_e[NN];
__device__ double g_pb[NBD], g_pe[NBD];
__device__ int g_Ri[NN];
__device__ float g_Rb[NN];
__device__ int g_Jj[NN];
__device__ float g_Je[NN];
__device__ unsigned long long g_keys[GCAP];

// ---------- GEMV: warp per row, float4 ----------
__global__ void __launch_bounds__(1024) k_dots(const float* __restrict__ G,
                                               const float* __restrict__ wb,
                                               const float* __restrict__ we) {
    int wib = threadIdx.x >> 5;
    int lane = threadIdx.x & 31;
    int row = blockIdx.x * 32 + wib;
    const float4* rp = reinterpret_cast<const float4*>(G + (size_t)row * DDIM);
    const float4* wb4 = reinterpret_cast<const float4*>(wb);
    const float4* we4 = reinterpret_cast<const float4*>(we);
    float sb = 0.f, se = 0.f;
#pragma unroll
    for (int t = 0; t < 2; t++) {
        int q = lane + 32 * t;
        if (q < DDIM / 4) {
            float4 g = rp[q];
            float4 b4 = __ldg(&wb4[q]);
            float4 e4 = __ldg(&we4[q]);
            sb = fmaf(g.x, b4.x, fmaf(g.y, b4.y, fmaf(g.z, b4.z, fmaf(g.w, b4.w, sb))));
            se = fmaf(g.x, e4.x, fmaf(g.y, e4.y, fmaf(g.z, e4.z, fmaf(g.w, e4.w, se))));
        }
    }
#pragma unroll
    for (int o = 16; o; o >>= 1) {
        sb += __shfl_xor_sync(0xffffffffu, sb, o);
        se += __shfl_xor_sync(0xffffffffu, se, o);
    }
    __shared__ double eb[32], ee[32];
    if (lane == 0) {
        g_b[row] = sb;
        g_e[row] = se;
        eb[wib] = (double)expf(sb);
        ee[wib] = (double)expf(se);
    }
    __syncthreads();
    if (threadIdx.x == 0) {
        double a = 0.0, b = 0.0;
#pragma unroll
        for (int w = 0; w < 32; w++) { a += eb[w]; b += ee[w]; }
        g_pb[blockIdx.x] = a;
        g_pe[blockIdx.x] = b;
    }
}

__device__ __forceinline__ unsigned f2u(float x) {
    unsigned u = __float_as_uint(x);
    return (u & 0x80000000u) ? ~u : (u | 0x80000000u);
}
__device__ __forceinline__ float u2f(unsigned u) {
    unsigned v = (u & 0x80000000u) ? (u & 0x7FFFFFFFu) : ~u;
    return __uint_as_float(v);
}

__global__ void __launch_bounds__(1024) k_master(const int* __restrict__ kp,
                                                 float* __restrict__ out,
                                                 int out_size) {
    __shared__ __align__(16) unsigned long long cand[SCAP];   // 24KB
    __shared__ unsigned hist[NBIN];                           // 8KB
    __shared__ int sjidx[JCAP];
    __shared__ float sje[JCAP];                               // 8KB
    __shared__ int sri[RCAP];
    __shared__ float srb[RCAP];                               // 2KB
    __shared__ unsigned long long stop[GATH];                 // 4KB
    __shared__ float wtot[32], wexcl[32], stot[32], sexcl[32];
    __shared__ double sda[8], sdb[8];
    __shared__ float s_denom;
    __shared__ unsigned s_umin, s_umax, s_vmin, s_vmax;
    __shared__ unsigned s_ulow, s_vlow;
    __shared__ int s_nR, s_nJ, s_cnt;
    __shared__ unsigned s_m;

    int tid = threadIdx.x;
    int lane = tid & 31;
    int wid = tid >> 5;
    int k = *kp;
    if (k < 1) k = 1;
    if (k > KMAX) k = KMAX;
    int base = tid * 8;

    // ---- load working set into registers ----
    float bi[8], el[8], sl[8], cl[8];
#pragma unroll
    for (int t = 0; t < 8; t++) bi[t] = g_b[base + t];
#pragma unroll
    for (int t = 0; t < 8; t++) el[t] = g_e[base + t];

    // local prefix-max(b) / suffix-max(e) partials
    float lex, lex2;
    {
        float run = -INFINITY;
#pragma unroll
        for (int t = 0; t < 8; t++) { run = fmaxf(run, bi[t]); cl[t] = run; }
        float incl = run;
#pragma unroll
        for (int o = 1; o < 32; o <<= 1) {
            float u = __shfl_up_sync(0xffffffffu, incl, o);
            if (lane >= o) incl = fmaxf(incl, u);
        }
        if (lane == 31) wtot[wid] = incl;
        lex = __shfl_up_sync(0xffffffffu, incl, 1);
        if (lane == 0) lex = -INFINITY;
    }
    {
        float run = -INFINITY;
#pragma unroll
        for (int t = 7; t >= 0; t--) { run = fmaxf(run, el[t]); sl[t] = run; }
        float incl = run;
#pragma unroll
        for (int o = 1; o < 32; o <<= 1) {
            float u = __shfl_down_sync(0xffffffffu, incl, o);
            if (lane + o < 32) incl = fmaxf(incl, u);
        }
        if (lane == 0) stot[wid] = incl;
        lex2 = __shfl_down_sync(0xffffffffu, incl, 1);
        if (lane == 31) lex2 = -INFINITY;
    }
    // denominator partial reduce
    if (wid < 16) {
        double dv = (tid < 256) ? g_pb[tid] : g_pe[tid - 256];
#pragma unroll
        for (int o = 16; o; o >>= 1) dv += __shfl_down_sync(0xffffffffu, dv, o);
        if (lane == 0) { if (wid < 8) sda[wid] = dv; else sdb[wid - 8] = dv; }
    }
    // hist clear + scalar init
    if (tid >= 512 && tid < 512 + NBIN / 4) {
        int h4 = (tid - 512) * 4;
        *reinterpret_cast<uint4*>(&hist[h4]) = make_uint4(0u, 0u, 0u, 0u);
    }
    if (tid == 0) {
        s_nR = 0; s_nJ = 0; s_m = 0; s_cnt = 0;
        s_umin = ~0u; s_umax = 0u; s_vmin = ~0u; s_vmax = 0u;
    }
    __syncthreads();  // bar1

    if (wid == 0) {
        float incl = wtot[lane];
#pragma unroll
        for (int o = 1; o < 32; o <<= 1) {
            float u = __shfl_up_sync(0xffffffffu, incl, o);
            if (lane >= o) incl = fmaxf(incl, u);
        }
        float ex = __shfl_up_sync(0xffffffffu, incl, 1);
        if (lane == 0) ex = -INFINITY;
        wexcl[lane] = ex;
    } else if (wid == 1) {
        float incl = stot[lane];
#pragma unroll
        for (int o = 1; o < 32; o <<= 1) {
            float u = __shfl_down_sync(0xffffffffu, incl, o);
            if (lane + o < 32) incl = fmaxf(incl, u);
        }
        float ex = __shfl_down_sync(0xffffffffu, incl, 1);
        if (lane == 31) ex = -INFINITY;
        sexcl[lane] = ex;
    } else if (tid == 64) {
        double a = 0.0, b2 = 0.0;
#pragma unroll
        for (int w = 0; w < 8; w++) { a += sda[w]; b2 += sdb[w]; }
        s_denom = (float)(a * b2);
    }
    __syncthreads();  // bar2

    // finalize c_j and suffix-max; per-warp c min/max -> shared atomics
    {
        float exP = fmaxf(wexcl[wid], lex);
        float exS = fmaxf(sexcl[wid], lex2);
        unsigned lmin = ~0u, lmax = 0u;
#pragma unroll
        for (int t = 0; t < 8; t++) {
            cl[t] = fmaxf(cl[t], exP) + el[t];
            unsigned u = f2u(cl[t]);
            lmin = min(lmin, u);
            lmax = max(lmax, u);
        }
#pragma unroll
        for (int t = 0; t < 8; t++) sl[t] = fmaxf(sl[t], exS);
#pragma unroll
        for (int o = 16; o; o >>= 1) {
            lmin = min(lmin, __shfl_xor_sync(0xffffffffu, lmin, o));
            lmax = max(lmax, __shfl_xor_sync(0xffffffffu, lmax, o));
        }
        if (lane == 0) {
            atomicMin(&s_umin, lmin);
            atomicMax(&s_umax, lmax);
        }
    }
    __syncthreads();  // bar3

    // ---- select-1: one-pass linear-bin histogram over f2u(c) ----
    unsigned umin = s_umin;
    unsigned long long urange1 = (unsigned long long)(s_umax - umin) + 1ull;
#pragma unroll
    for (int t = 0; t < 8; t++) {
        unsigned u = f2u(cl[t]);
        unsigned bin = (unsigned)(((unsigned long long)(u - umin) * NBIN) / urange1);
        atomicAdd(&hist[bin], 1u);
    }
    __syncthreads();  // bar4
    if (wid == 0) {
        // lane owns bins [lane*64, lane*64+63]; find k-th-largest's bin (descending)
        int lsum = 0;
        int hb = lane * 64;
#pragma unroll
        for (int t = 0; t < 64; t++) lsum += (int)hist[hb + t];
        int suf = lsum;
#pragma unroll
        for (int o = 1; o < 32; o <<= 1) {
            int u = __shfl_down_sync(0xffffffffu, suf, o);
            if (lane + o < 32) suf += u;
        }
        int runc = suf - lsum;  // count in higher lanes (higher bins)
        for (int t = 63; t >= 0; t--) {
            int h = (int)hist[hb + t];
            if (k > runc && k <= runc + h) {
                unsigned bin = (unsigned)(hb + t);
                s_ulow = umin + (unsigned)(((unsigned long long)bin * urange1) >> 11);
            }
            runc += h;
        }
    }
    __syncthreads();  // bar5  (NO concurrent hist writes while warp0 reads!)
    unsigned ulow = s_ulow;
    float T = u2f(ulow);

    // ---- build J and R lists from registers; clear hist for select-2 ----
#pragma unroll
    for (int t = 0; t < 8; t++) {
        if (f2u(cl[t]) >= ulow) {
            int p = atomicAdd(&s_nJ, 1);
            if (p < JCAP) { sjidx[p] = base + t; sje[p] = el[t]; }
            else { g_Jj[p] = base + t; g_Je[p] = el[t]; }
        }
    }
#pragma unroll
    for (int t = 0; t < 8; t++) {
        if (bi[t] + sl[t] >= T) {
            int p = atomicAdd(&s_nR, 1);
            if (p < RCAP) { sri[p] = base + t; srb[p] = bi[t]; }
            else { g_Ri[p] = base + t; g_Rb[p] = bi[t]; }
        }
    }
    if (tid >= 512 && tid < 512 + NBIN / 4) {   // clear AFTER binfind barrier
        int h4 = (tid - 512) * 4;
        *reinterpret_cast<uint4*>(&hist[h4]) = make_uint4(0u, 0u, 0u, 0u);
    }
    __syncthreads();  // bar6

    // ---- enumerate R x J (warp per row); track value-bit min/max ----
    {
        int nR = s_nR, nJ = s_nJ;
        unsigned lvmin = ~0u, lvmax = 0u;
        for (int r = wid; r < nR; r += 32) {
            int i = (r < RCAP) ? sri[r] : g_Ri[r];
            float bv = (r < RCAP) ? srb[r] : g_Rb[r];
            float t2 = T - bv;
            for (int q = lane; q < nJ; q += 32) {
                int j;
                float ej;
                if (q < JCAP) { j = sjidx[q]; ej = sje[q]; }
                else { j = g_Jj[q]; ej = g_Je[q]; }
                if (j >= i && ej >= t2) {
                    float v = expf(bv + ej);
                    unsigned vb = __float_as_uint(v);
                    unsigned fl = (unsigned)i * NN + (unsigned)j;
                    unsigned long long key = ((unsigned long long)vb << 32) |
                                             (unsigned long long)(0xFFFFFFFFu - fl);
                    unsigned p = atomicAdd(&s_m, 1u);
                    if (p < SCAP) cand[p] = key;
                    else if (p < GCAP) g_keys[p] = key;
                    lvmin = min(lvmin, vb);
                    lvmax = max(lvmax, vb);
                }
            }
        }
#pragma unroll
        for (int o = 16; o; o >>= 1) {
            lvmin = min(lvmin, __shfl_xor_sync(0xffffffffu, lvmin, o));
            lvmax = max(lvmax, __shfl_xor_sync(0xffffffffu, lvmax, o));
        }
        if (lane == 0) {
            atomicMin(&s_vmin, lvmin);
            atomicMax(&s_vmax, lvmax);
        }
    }
    __syncthreads();  // bar7
    unsigned M = s_m;
    if (M > (unsigned)GCAP) M = (unsigned)GCAP;
    unsigned vmin = s_vmin;
    unsigned long long vrange1 = (unsigned long long)(s_vmax - vmin) + 1ull;

    // ---- select-2: one-pass linear-bin histogram over value bits ----
    for (unsigned c = tid; c < M; c += 1024) {
        unsigned vb = (unsigned)(((c < SCAP) ? cand[c] : g_keys[c]) >> 32);
        unsigned bin = (unsigned)(((unsigned long long)(vb - vmin) * NBIN) / vrange1);
        atomicAdd(&hist[bin], 1u);
    }
    __syncthreads();  // bar8
    if (wid == 0) {
        int lsum = 0;
        int hb = lane * 64;
#pragma unroll
        for (int t = 0; t < 64; t++) lsum += (int)hist[hb + t];
        int suf = lsum;
#pragma unroll
        for (int o = 1; o < 32; o <<= 1) {
            int u = __shfl_down_sync(0xffffffffu, suf, o);
            if (lane + o < 32) suf += u;
        }
        int runc = suf - lsum;
        for (int t = 63; t >= 0; t--) {
            int h = (int)hist[hb + t];
            if (k > runc && k <= runc + h) {
                unsigned bin = (unsigned)(hb + t);
                s_vlow = vmin + (unsigned)(((unsigned long long)bin * vrange1) >> 11);
            }
            runc += h;
        }
        // if M <= k no bin satisfies rank condition via above when k > M; guard:
        if (lane == 0 && (int)M <= k) s_vlow = vmin;
    }
    __syncthreads();  // bar9

    // ---- gather all candidates with value-bits >= vlow (superset of top-k) ----
    {
        unsigned vlow = s_vlow;
        for (unsigned c = tid; c < M; c += 1024) {
            unsigned long long key = (c < SCAP) ? cand[c] : g_keys[c];
            if ((unsigned)(key >> 32) >= vlow) {
                int p = atomicAdd(&s_cnt, 1);
                if (p < GATH) stop[p] = key;
            }
        }
    }
    __syncthreads();  // bar10
    int n = s_cnt;
    if (n > GATH) n = GATH;

    // ---- exact rank sort over gathered keys (value desc, flat idx asc) ----
    float denom = s_denom;
    if (tid < n) {
        unsigned long long mykey = stop[tid];
        int rank = 0;
        for (int u = 0; u < n; u++) rank += (stop[u] > mykey);
        if (rank < k) {
            unsigned fl = 0xFFFFFFFFu - (unsigned)(mykey & 0xFFFFFFFFull);
            unsigned ii = fl / NN, jj = fl % NN;
            float v = __uint_as_float((unsigned)(mykey >> 32));
            if (2 * rank + 1 < out_size) {
                out[2 * rank] = (float)ii;
                out[2 * rank + 1] = (float)jj;
            }
            if (2 * k + rank < out_size) out[2 * k + rank] = v / denom;
        }
    }
    for (int c = 3 * k + tid; c < out_size; c += 1024) out[c] = 0.f;
}

extern "C" void kernel_launch(void* const* d_in, const int* in_sizes, int n_in,
                              void* d_out, int out_size) {
    const float* G = (const float*)d_in[0];
    const float* wb = (const float*)d_in[1];
    const float* we = (const float*)d_in[2];
    const int* kp = (const int*)d_in[3];
    float* out = (float*)d_out;

    k_dots<<<NBD, 1024>>>(G, wb, we);
    k_master<<<1, 1024>>>(kp, out, out_size);
}

// round 9
// speedup vs baseline: 1.3339x; 1.0471x over previous
#include <cuda_runtime.h>
#include <math.h>

#define NN 8192
#define DDIM 200
#define NBD 256
#define GCAP (1 << 18)
#define SCAP 3072
#define JCAP 1024
#define RCAP 256
#define GATH 512
#define NBIN 2048
#define KMAX 128

__device__ float g_b[NN], g_e[NN];
__device__ float g_pb[NBD], g_pe[NBD];
__device__ int g_Ri[NN];
__device__ float g_Rb[NN];
__device__ int g_Jj[NN];
__device__ float g_Je[NN];
__device__ unsigned long long g_keys[GCAP];

// ---------- GEMV: warp per row, float4; float partial exp-sums ----------
__global__ void __launch_bounds__(1024) k_dots(const float* __restrict__ G,
                                               const float* __restrict__ wb,
                                               const float* __restrict__ we) {
    int wib = threadIdx.x >> 5;
    int lane = threadIdx.x & 31;
    int row = blockIdx.x * 32 + wib;
    const float4* rp = reinterpret_cast<const float4*>(G + (size_t)row * DDIM);
    const float4* wb4 = reinterpret_cast<const float4*>(wb);
    const float4* we4 = reinterpret_cast<const float4*>(we);
    float sb = 0.f, se = 0.f;
#pragma unroll
    for (int t = 0; t < 2; t++) {
        int q = lane + 32 * t;
        if (q < DDIM / 4) {
            float4 g = rp[q];
            float4 b4 = __ldg(&wb4[q]);
            float4 e4 = __ldg(&we4[q]);
            sb = fmaf(g.x, b4.x, fmaf(g.y, b4.y, fmaf(g.z, b4.z, fmaf(g.w, b4.w, sb))));
            se = fmaf(g.x, e4.x, fmaf(g.y, e4.y, fmaf(g.z, e4.z, fmaf(g.w, e4.w, se))));
        }
    }
#pragma unroll
    for (int o = 16; o; o >>= 1) {
        sb += __shfl_xor_sync(0xffffffffu, sb, o);
        se += __shfl_xor_sync(0xffffffffu, se, o);
    }
    __shared__ float eb[32], ee[32];
    if (lane == 0) {
        g_b[row] = sb;
        g_e[row] = se;
        eb[wib] = expf(sb);
        ee[wib] = expf(se);
    }
    __syncthreads();
    if (wib == 0) {
        float v = eb[lane];
#pragma unroll
        for (int o = 16; o; o >>= 1) v += __shfl_down_sync(0xffffffffu, v, o);
        if (lane == 0) g_pb[blockIdx.x] = v;
    } else if (wib == 1) {
        float v = ee[lane];
#pragma unroll
        for (int o = 16; o; o >>= 1) v += __shfl_down_sync(0xffffffffu, v, o);
        if (lane == 0) g_pe[blockIdx.x] = v;
    }
}

__device__ __forceinline__ unsigned f2u(float x) {
    unsigned u = __float_as_uint(x);
    return (u & 0x80000000u) ? ~u : (u | 0x80000000u);
}
__device__ __forceinline__ float u2f(unsigned u) {
    unsigned v = (u & 0x80000000u) ? (u & 0x7FFFFFFFu) : ~u;
    return __uint_as_float(v);
}

// one-warp bin-find over hist[NBIN], descending rank k_in -> s_kbin (tid<32)
#define BIN_FIND(k_in)                                                           \
    do {                                                                         \
        int lsum = 0;                                                            \
        int hb = tid * (NBIN / 32);                                              \
        _Pragma("unroll") for (int t = 0; t < NBIN / 32; t++)                    \
            lsum += (int)hist[hb + t];                                           \
        int suf = lsum;                                                          \
        _Pragma("unroll") for (int o = 1; o < 32; o <<= 1) {                     \
            int u = __shfl_down_sync(0xffffffffu, suf, o);                       \
            if (tid + o < 32) suf += u;                                          \
        }                                                                        \
        int runc = suf - lsum;                                                   \
        for (int t = NBIN / 32 - 1; t >= 0; t--) {                               \
            int h = (int)hist[hb + t];                                           \
            if ((k_in) > runc && (k_in) <= runc + h) s_kbin = hb + t;            \
            runc += h;                                                           \
        }                                                                        \
    } while (0)

__global__ void __launch_bounds__(1024) k_master(const int* __restrict__ kp,
                                                 float* __restrict__ out,
                                                 int out_size) {
    __shared__ __align__(16) unsigned long long cand[SCAP];   // 24KB
    __shared__ unsigned hist[NBIN];                           // 8KB
    __shared__ int sjidx[JCAP];
    __shared__ float sje[JCAP];                               // 8KB
    __shared__ int sri[RCAP];
    __shared__ float srb[RCAP];                               // 2KB
    __shared__ unsigned long long stop[GATH];                 // 4KB
    __shared__ float wtot[32], wexcl[32], stot[32], sexcl[32];
    __shared__ float sda[8], sdb[8];
    __shared__ float s_denom;
    __shared__ unsigned s_umin, s_umax, s_vmin, s_vmax;
    __shared__ int s_kbin;
    __shared__ int s_nR, s_nJ, s_cnt;
    __shared__ unsigned s_m;

    int tid = threadIdx.x;
    int lane = tid & 31;
    int wid = tid >> 5;
    int k = *kp;
    if (k < 1) k = 1;
    if (k > KMAX) k = KMAX;
    int base = tid * 8;

    // ---- load working set into registers ----
    float bi[8], el[8], sl[8], cl[8];
#pragma unroll
    for (int t = 0; t < 8; t++) bi[t] = g_b[base + t];
#pragma unroll
    for (int t = 0; t < 8; t++) el[t] = g_e[base + t];

    // local prefix-max(b) / suffix-max(e) partials
    float lex, lex2;
    {
        float run = -INFINITY;
#pragma unroll
        for (int t = 0; t < 8; t++) { run = fmaxf(run, bi[t]); cl[t] = run; }
        float incl = run;
#pragma unroll
        for (int o = 1; o < 32; o <<= 1) {
            float u = __shfl_up_sync(0xffffffffu, incl, o);
            if (lane >= o) incl = fmaxf(incl, u);
        }
        if (lane == 31) wtot[wid] = incl;
        lex = __shfl_up_sync(0xffffffffu, incl, 1);
        if (lane == 0) lex = -INFINITY;
    }
    {
        float run = -INFINITY;
#pragma unroll
        for (int t = 7; t >= 0; t--) { run = fmaxf(run, el[t]); sl[t] = run; }
        float incl = run;
#pragma unroll
        for (int o = 1; o < 32; o <<= 1) {
            float u = __shfl_down_sync(0xffffffffu, incl, o);
            if (lane + o < 32) incl = fmaxf(incl, u);
        }
        if (lane == 0) stot[wid] = incl;
        lex2 = __shfl_down_sync(0xffffffffu, incl, 1);
        if (lane == 31) lex2 = -INFINITY;
    }
    // denominator partial reduce (float)
    if (wid < 16) {
        float dv = (tid < 256) ? g_pb[tid] : g_pe[tid - 256];
#pragma unroll
        for (int o = 16; o; o >>= 1) dv += __shfl_down_sync(0xffffffffu, dv, o);
        if (lane == 0) { if (wid < 8) sda[wid] = dv; else sdb[wid - 8] = dv; }
    }
    // hist clear + scalar init
    if (tid >= 512 && tid < 512 + NBIN / 4) {
        int h4 = (tid - 512) * 4;
        *reinterpret_cast<uint4*>(&hist[h4]) = make_uint4(0u, 0u, 0u, 0u);
    }
    if (tid == 0) {
        s_nR = 0; s_nJ = 0; s_m = 0; s_cnt = 0;
        s_umin = ~0u; s_umax = 0u; s_vmin = ~0u; s_vmax = 0u;
    }
    __syncthreads();  // bar1

    if (wid == 0) {
        float incl = wtot[lane];
#pragma unroll
        for (int o = 1; o < 32; o <<= 1) {
            float u = __shfl_up_sync(0xffffffffu, incl, o);
            if (lane >= o) incl = fmaxf(incl, u);
        }
        float ex = __shfl_up_sync(0xffffffffu, incl, 1);
        if (lane == 0) ex = -INFINITY;
        wexcl[lane] = ex;
    } else if (wid == 1) {
        float incl = stot[lane];
#pragma unroll
        for (int o = 1; o < 32; o <<= 1) {
            float u = __shfl_down_sync(0xffffffffu, incl, o);
            if (lane + o < 32) incl = fmaxf(incl, u);
        }
        float ex = __shfl_down_sync(0xffffffffu, incl, 1);
        if (lane == 31) ex = -INFINITY;
        sexcl[lane] = ex;
    } else if (tid == 64) {
        float a = 0.f, b2 = 0.f;
#pragma unroll
        for (int w = 0; w < 8; w++) { a += sda[w]; b2 += sdb[w]; }
        s_denom = a * b2;
    }
    __syncthreads();  // bar2

    // finalize c_j and suffix-max; per-warp c min/max -> shared atomics
    {
        float exP = fmaxf(wexcl[wid], lex);
        float exS = fmaxf(sexcl[wid], lex2);
        unsigned lmin = ~0u, lmax = 0u;
#pragma unroll
        for (int t = 0; t < 8; t++) {
            cl[t] = fmaxf(cl[t], exP) + el[t];
            unsigned u = f2u(cl[t]);
            lmin = min(lmin, u);
            lmax = max(lmax, u);
        }
#pragma unroll
        for (int t = 0; t < 8; t++) sl[t] = fmaxf(sl[t], exS);
#pragma unroll
        for (int o = 16; o; o >>= 1) {
            lmin = min(lmin, __shfl_xor_sync(0xffffffffu, lmin, o));
            lmax = max(lmax, __shfl_xor_sync(0xffffffffu, lmax, o));
        }
        if (lane == 0) {
            atomicMin(&s_umin, lmin);
            atomicMax(&s_umax, lmax);
        }
    }
    __syncthreads();  // bar3

    // ---- select-1: one-pass histogram, fixed-point reciprocal binning ----
    unsigned umin = s_umin;
    unsigned long long sc1 =
        ((unsigned long long)NBIN << 32) /
        ((unsigned long long)(s_umax - umin) + 1ull);   // one div per thread
#pragma unroll
    for (int t = 0; t < 8; t++) {
        unsigned bin = (unsigned)(((unsigned long long)(f2u(cl[t]) - umin) * sc1) >> 32);
        atomicAdd(&hist[bin], 1u);
    }
    __syncthreads();  // bar4
    if (wid == 0) BIN_FIND(k);
    __syncthreads();  // bar5
    // exact lower edge of the k-th bin (predicate-equivalent to bin >= kbin)
    unsigned ulow;
    {
        unsigned long long kb = (unsigned long long)s_kbin << 32;
        ulow = umin + (unsigned)((kb + sc1 - 1ull) / sc1);   // one div per thread
    }
    float T = u2f(ulow);

    // ---- build J and R lists from registers; clear hist for select-2 ----
#pragma unroll
    for (int t = 0; t < 8; t++) {
        if (f2u(cl[t]) >= ulow) {
            int p = atomicAdd(&s_nJ, 1);
            if (p < JCAP) { sjidx[p] = base + t; sje[p] = el[t]; }
            else { g_Jj[p] = base + t; g_Je[p] = el[t]; }
        }
    }
#pragma unroll
    for (int t = 0; t < 8; t++) {
        if (bi[t] + sl[t] >= T) {
            int p = atomicAdd(&s_nR, 1);
            if (p < RCAP) { sri[p] = base + t; srb[p] = bi[t]; }
            else { g_Ri[p] = base + t; g_Rb[p] = bi[t]; }
        }
    }
    if (tid >= 512 && tid < 512 + NBIN / 4) {   // clear AFTER binfind barrier
        int h4 = (tid - 512) * 4;
        *reinterpret_cast<uint4*>(&hist[h4]) = make_uint4(0u, 0u, 0u, 0u);
    }
    __syncthreads();  // bar6

    // ---- enumerate R x J (warp per row); track value-bit min/max ----
    {
        int nR = s_nR, nJ = s_nJ;
        unsigned lvmin = ~0u, lvmax = 0u;
        for (int r = wid; r < nR; r += 32) {
            int i = (r < RCAP) ? sri[r] : g_Ri[r];
            float bv = (r < RCAP) ? srb[r] : g_Rb[r];
            float t2 = T - bv;
            for (int q = lane; q < nJ; q += 32) {
                int j;
                float ej;
                if (q < JCAP) { j = sjidx[q]; ej = sje[q]; }
                else { j = g_Jj[q]; ej = g_Je[q]; }
                if (j >= i && ej >= t2) {
                    float v = expf(bv + ej);
                    unsigned vb = __float_as_uint(v);
                    unsigned fl = (unsigned)i * NN + (unsigned)j;
                    unsigned long long key = ((unsigned long long)vb << 32) |
                                             (unsigned long long)(0xFFFFFFFFu - fl);
                    unsigned p = atomicAdd(&s_m, 1u);
                    if (p < SCAP) cand[p] = key;
                    else if (p < GCAP) g_keys[p] = key;
                    lvmin = min(lvmin, vb);
                    lvmax = max(lvmax, vb);
                }
            }
        }
#pragma unroll
        for (int o = 16; o; o >>= 1) {
            lvmin = min(lvmin, __shfl_xor_sync(0xffffffffu, lvmin, o));
            lvmax = max(lvmax, __shfl_xor_sync(0xffffffffu, lvmax, o));
        }
        if (lane == 0) {
            atomicMin(&s_vmin, lvmin);
            atomicMax(&s_vmax, lvmax);
        }
    }
    __syncthreads();  // bar7
    unsigned M = s_m;
    if (M > (unsigned)GCAP) M = (unsigned)GCAP;
    unsigned vmin = s_vmin;
    unsigned long long sc2 =
        ((unsigned long long)NBIN << 32) /
        ((unsigned long long)(s_vmax - vmin) + 1ull);

    // ---- select-2: one-pass histogram over value bits (mul-shift binning) ----
    for (unsigned c = tid; c < M; c += 1024) {
        unsigned vb = (unsigned)(((c < SCAP) ? cand[c] : g_keys[c]) >> 32);
        unsigned bin = (unsigned)(((unsigned long long)(vb - vmin) * sc2) >> 32);
        atomicAdd(&hist[bin], 1u);
    }
    __syncthreads();  // bar8
    if (wid == 0) {
        BIN_FIND(k);
        if (lane == 0 && (int)M <= k) s_kbin = 0;   // gather everything
    }
    __syncthreads();  // bar9
    unsigned vlow;
    {
        unsigned long long kb = (unsigned long long)s_kbin << 32;
        vlow = vmin + (unsigned)((kb + sc2 - 1ull) / sc2);
    }

    // ---- gather all candidates with value-bits >= vlow (superset of top-k) ----
    for (unsigned c = tid; c < M; c += 1024) {
        unsigned long long key = (c < SCAP) ? cand[c] : g_keys[c];
        if ((unsigned)(key >> 32) >= vlow) {
            int p = atomicAdd(&s_cnt, 1);
            if (p < GATH) stop[p] = key;
        }
    }
    __syncthreads();  // bar10
    int n = s_cnt;
    if (n > GATH) n = GATH;

    // ---- exact rank sort over gathered keys (value desc, flat idx asc) ----
    float denom = s_denom;
    if (tid < n) {
        unsigned long long mykey = stop[tid];
        int rank = 0;
        for (int u = 0; u < n; u++) rank += (stop[u] > mykey);
        if (rank < k) {
            unsigned fl = 0xFFFFFFFFu - (unsigned)(mykey & 0xFFFFFFFFull);
            unsigned ii = fl / NN, jj = fl % NN;
            float v = __uint_as_float((unsigned)(mykey >> 32));
            if (2 * rank + 1 < out_size) {
                out[2 * rank] = (float)ii;
                out[2 * rank + 1] = (float)jj;
            }
            if (2 * k + rank < out_size) out[2 * k + rank] = v / denom;
        }
    }
    for (int c = 3 * k + tid; c < out_size; c += 1024) out[c] = 0.f;
}

extern "C" void kernel_launch(void* const* d_in, const int* in_sizes, int n_in,
                              void* d_out, int out_size) {
    const float* G = (const float*)d_in[0];
    const float* wb = (const float*)d_in[1];
    const float* we = (const float*)d_in[2];
    const int* kp = (const int*)d_in[3];
    float* out = (float*)d_out;

    k_dots<<<NBD, 1024>>>(G, wb, we);
    k_master<<<1, 1024>>>(kp, out, out_size);
}

// round 10
// speedup vs baseline: 2.7917x; 2.0928x over previous
#include <cuda_runtime.h>
#include <math.h>

#define NN 8192
#define DDIM 200
#define NBD 256
#define GCAP (1 << 18)
#define SCAP 3072
#define JCAP 1024
#define RCAP 256
#define GATH 512
#define NBIN 896
#define KMAX 128

__device__ float g_b[NN], g_e[NN];
__device__ float g_pb[NBD], g_pe[NBD];
__device__ int g_Ri[NN];
__device__ float g_Rb[NN];
__device__ int g_Jj[NN];
__device__ float g_Je[NN];
__device__ unsigned long long g_keys[GCAP];

// ---------- GEMV: warp per row, float4; float partial exp-sums ----------
__global__ void __launch_bounds__(1024) k_dots(const float* __restrict__ G,
                                               const float* __restrict__ wb,
                                               const float* __restrict__ we) {
    int wib = threadIdx.x >> 5;
    int lane = threadIdx.x & 31;
    int row = blockIdx.x * 32 + wib;
    const float4* rp = reinterpret_cast<const float4*>(G + (size_t)row * DDIM);
    const float4* wb4 = reinterpret_cast<const float4*>(wb);
    const float4* we4 = reinterpret_cast<const float4*>(we);
    float sb = 0.f, se = 0.f;
#pragma unroll
    for (int t = 0; t < 2; t++) {
        int q = lane + 32 * t;
        if (q < DDIM / 4) {
            float4 g = rp[q];
            float4 b4 = __ldg(&wb4[q]);
            float4 e4 = __ldg(&we4[q]);
            sb = fmaf(g.x, b4.x, fmaf(g.y, b4.y, fmaf(g.z, b4.z, fmaf(g.w, b4.w, sb))));
            se = fmaf(g.x, e4.x, fmaf(g.y, e4.y, fmaf(g.z, e4.z, fmaf(g.w, e4.w, se))));
        }
    }
#pragma unroll
    for (int o = 16; o; o >>= 1) {
        sb += __shfl_xor_sync(0xffffffffu, sb, o);
        se += __shfl_xor_sync(0xffffffffu, se, o);
    }
    __shared__ float eb[32], ee[32];
    if (lane == 0) {
        g_b[row] = sb;
        g_e[row] = se;
        eb[wib] = expf(sb);
        ee[wib] = expf(se);
    }
    __syncthreads();
    if (wib == 0) {
        float v = eb[lane];
#pragma unroll
        for (int o = 16; o; o >>= 1) v += __shfl_down_sync(0xffffffffu, v, o);
        if (lane == 0) g_pb[blockIdx.x] = v;
    } else if (wib == 1) {
        float v = ee[lane];
#pragma unroll
        for (int o = 16; o; o >>= 1) v += __shfl_down_sync(0xffffffffu, v, o);
        if (lane == 0) g_pe[blockIdx.x] = v;
    }
}

__device__ __forceinline__ unsigned f2u(float x) {
    unsigned u = __float_as_uint(x);
    return (u & 0x80000000u) ? ~u : (u | 0x80000000u);
}
__device__ __forceinline__ float u2f(unsigned u) {
    unsigned v = (u & 0x80000000u) ? (u & 0x7FFFFFFFu) : ~u;
    return __uint_as_float(v);
}

// log-linear bin of distance d (monotone non-decreasing in d), bins [0, NBIN)
__device__ __forceinline__ int logbin(unsigned d) {
    if (d < 32u) return (int)d;
    int m = 31 - __clz(d);  // >= 5
    return ((m - 5) << 5) + (int)((d >> (m - 5)) & 31u) + 32;
}
// smallest d with logbin(d) == b  (64-bit to handle b == NBIN)
__device__ __forceinline__ unsigned long long binlow(int b) {
    if (b < 32) return (unsigned long long)b;
    int m = 5 + ((b - 32) >> 5);
    int sub = (b - 32) & 31;
    return (unsigned long long)(32 + sub) << (m - 5);
}

// one-warp ascending bin-find over hist[NBIN]: smallest bin with cum >= k_in
#define BIN_FIND_ASC(k_in)                                                       \
    do {                                                                         \
        int lsum = 0;                                                            \
        int hb = tid * (NBIN / 32);                                              \
        _Pragma("unroll") for (int t = 0; t < NBIN / 32; t++)                    \
            lsum += (int)hist[hb + t];                                           \
        int pre = lsum;                                                          \
        _Pragma("unroll") for (int o = 1; o < 32; o <<= 1) {                     \
            int u = __shfl_up_sync(0xffffffffu, pre, o);                         \
            if (tid >= o) pre += u;                                              \
        }                                                                        \
        int runc = pre - lsum;                                                   \
        for (int t = 0; t < NBIN / 32; t++) {                                    \
            int h = (int)hist[hb + t];                                           \
            if (runc < (k_in) && runc + h >= (k_in)) s_kbin = hb + t;            \
            runc += h;                                                           \
        }                                                                        \
    } while (0)

__global__ void __launch_bounds__(1024) k_master(const int* __restrict__ kp,
                                                 float* __restrict__ out,
                                                 int out_size) {
    __shared__ __align__(16) unsigned long long cand[SCAP];   // 24KB
    __shared__ __align__(16) unsigned hist[NBIN];             // 3.5KB
    __shared__ int sjidx[JCAP];
    __shared__ float sje[JCAP];                               // 8KB
    __shared__ int sri[RCAP];
    __shared__ float srb[RCAP];                               // 2KB
    __shared__ unsigned long long stop[GATH];                 // 4KB
    __shared__ float wtot[32], wexcl[32], stot[32], sexcl[32];
    __shared__ float sda[8], sdb[8];
    __shared__ float s_denom;
    __shared__ unsigned s_umax, s_vmax;
    __shared__ int s_kbin;
    __shared__ int s_nR, s_nJ, s_cnt;
    __shared__ unsigned s_m;

    int tid = threadIdx.x;
    int lane = tid & 31;
    int wid = tid >> 5;
    int k = *kp;
    if (k < 1) k = 1;
    if (k > KMAX) k = KMAX;
    int base = tid * 8;

    // ---- load working set into registers (vectorized) ----
    float bi[8], el[8], sl[8], cl[8];
    {
        const float4* bp = reinterpret_cast<const float4*>(g_b) + tid * 2;
        const float4* ep = reinterpret_cast<const float4*>(g_e) + tid * 2;
        float4 b0 = bp[0], b1 = bp[1], e0 = ep[0], e1 = ep[1];
        bi[0] = b0.x; bi[1] = b0.y; bi[2] = b0.z; bi[3] = b0.w;
        bi[4] = b1.x; bi[5] = b1.y; bi[6] = b1.z; bi[7] = b1.w;
        el[0] = e0.x; el[1] = e0.y; el[2] = e0.z; el[3] = e0.w;
        el[4] = e1.x; el[5] = e1.y; el[6] = e1.z; el[7] = e1.w;
    }

    // local prefix-max(b) / suffix-max(e) partials
    float lex, lex2;
    {
        float run = -INFINITY;
#pragma unroll
        for (int t = 0; t < 8; t++) { run = fmaxf(run, bi[t]); cl[t] = run; }
        float incl = run;
#pragma unroll
        for (int o = 1; o < 32; o <<= 1) {
            float u = __shfl_up_sync(0xffffffffu, incl, o);
            if (lane >= o) incl = fmaxf(incl, u);
        }
        if (lane == 31) wtot[wid] = incl;
        lex = __shfl_up_sync(0xffffffffu, incl, 1);
        if (lane == 0) lex = -INFINITY;
    }
    {
        float run = -INFINITY;
#pragma unroll
        for (int t = 7; t >= 0; t--) { run = fmaxf(run, el[t]); sl[t] = run; }
        float incl = run;
#pragma unroll
        for (int o = 1; o < 32; o <<= 1) {
            float u = __shfl_down_sync(0xffffffffu, incl, o);
            if (lane + o < 32) incl = fmaxf(incl, u);
        }
        if (lane == 0) stot[wid] = incl;
        lex2 = __shfl_down_sync(0xffffffffu, incl, 1);
        if (lane == 31) lex2 = -INFINITY;
    }
    // denominator partial reduce (float)
    if (wid < 16) {
        float dv = (tid < 256) ? g_pb[tid] : g_pe[tid - 256];
#pragma unroll
        for (int o = 16; o; o >>= 1) dv += __shfl_down_sync(0xffffffffu, dv, o);
        if (lane == 0) { if (wid < 8) sda[wid] = dv; else sdb[wid - 8] = dv; }
    }
    // hist clear + scalar init
    if (tid >= 512 && tid < 512 + NBIN / 4) {
        int h4 = (tid - 512) * 4;
        *reinterpret_cast<uint4*>(&hist[h4]) = make_uint4(0u, 0u, 0u, 0u);
    }
    if (tid == 0) {
        s_nR = 0; s_nJ = 0; s_m = 0; s_cnt = 0;
        s_umax = 0u; s_vmax = 0u; s_kbin = NBIN - 1;
    }
    __syncthreads();  // bar1

    if (wid == 0) {
        float incl = wtot[lane];
#pragma unroll
        for (int o = 1; o < 32; o <<= 1) {
            float u = __shfl_up_sync(0xffffffffu, incl, o);
            if (lane >= o) incl = fmaxf(incl, u);
        }
        float ex = __shfl_up_sync(0xffffffffu, incl, 1);
        if (lane == 0) ex = -INFINITY;
        wexcl[lane] = ex;
    } else if (wid == 1) {
        float incl = stot[lane];
#pragma unroll
        for (int o = 1; o < 32; o <<= 1) {
            float u = __shfl_down_sync(0xffffffffu, incl, o);
            if (lane + o < 32) incl = fmaxf(incl, u);
        }
        float ex = __shfl_down_sync(0xffffffffu, incl, 1);
        if (lane == 31) ex = -INFINITY;
        sexcl[lane] = ex;
    } else if (tid == 64) {
        float a = 0.f, b2 = 0.f;
#pragma unroll
        for (int w = 0; w < 8; w++) { a += sda[w]; b2 += sdb[w]; }
        s_denom = a * b2;
    }
    __syncthreads();  // bar2

    // finalize c_j and suffix-max; per-warp c max -> shared atomic
    {
        float exP = fmaxf(wexcl[wid], lex);
        float exS = fmaxf(sexcl[wid], lex2);
        unsigned lmax = 0u;
#pragma unroll
        for (int t = 0; t < 8; t++) {
            cl[t] = fmaxf(cl[t], exP) + el[t];
            lmax = max(lmax, f2u(cl[t]));
        }
#pragma unroll
        for (int t = 0; t < 8; t++) sl[t] = fmaxf(sl[t], exS);
#pragma unroll
        for (int o = 16; o; o >>= 1)
            lmax = max(lmax, __shfl_xor_sync(0xffffffffu, lmax, o));
        if (lane == 0) atomicMax(&s_umax, lmax);
    }
    __syncthreads();  // bar3

    // ---- select-1: one-pass log-linear histogram on d = umax - f2u(c) ----
    unsigned umax = s_umax;
#pragma unroll
    for (int t = 0; t < 8; t++) {
        int bin = logbin(umax - f2u(cl[t]));
        atomicAdd(&hist[bin], 1u);
    }
    __syncthreads();  // bar4
    if (wid == 0) BIN_FIND_ASC(k);
    __syncthreads();  // bar5
    // exact threshold: u >= ulow  <=>  logbin(umax-u) <= kbin
    unsigned ulow;
    {
        unsigned long long dmax = binlow(s_kbin + 1) - 1ull;
        ulow = (dmax >= (unsigned long long)umax) ? 0u : umax - (unsigned)dmax;
    }
    float T = u2f(ulow);

    // ---- build J and R lists; clear hist; reset kbin ----
#pragma unroll
    for (int t = 0; t < 8; t++) {
        if (f2u(cl[t]) >= ulow) {
            int p = atomicAdd(&s_nJ, 1);
            if (p < JCAP) { sjidx[p] = base + t; sje[p] = el[t]; }
            else { g_Jj[p] = base + t; g_Je[p] = el[t]; }
        }
    }
#pragma unroll
    for (int t = 0; t < 8; t++) {
        if (bi[t] + sl[t] >= T) {
            int p = atomicAdd(&s_nR, 1);
            if (p < RCAP) { sri[p] = base + t; srb[p] = bi[t]; }
            else { g_Ri[p] = base + t; g_Rb[p] = bi[t]; }
        }
    }
    if (tid >= 512 && tid < 512 + NBIN / 4) {   // clear AFTER binfind consumed
        int h4 = (tid - 512) * 4;
        *reinterpret_cast<uint4*>(&hist[h4]) = make_uint4(0u, 0u, 0u, 0u);
    }
    __syncthreads();  // bar6

    // ---- enumerate R x J (warp per row); track value-bit max ----
    if (tid == 0) s_kbin = NBIN - 1;   // safe: consumed before bar6, re-read after bar9
    {
        int nR = s_nR, nJ = s_nJ;
        unsigned lvmax = 0u;
        for (int r = wid; r < nR; r += 32) {
            int i = (r < RCAP) ? sri[r] : g_Ri[r];
            float bv = (r < RCAP) ? srb[r] : g_Rb[r];
            float t2 = T - bv;
            for (int q = lane; q < nJ; q += 32) {
                int j;
                float ej;
                if (q < JCAP) { j = sjidx[q]; ej = sje[q]; }
                else { j = g_Jj[q]; ej = g_Je[q]; }
                if (j >= i && ej >= t2) {
                    float v = expf(bv + ej);
                    unsigned vb = __float_as_uint(v);
                    unsigned fl = (unsigned)i * NN + (unsigned)j;
                    unsigned long long key = ((unsigned long long)vb << 32) |
                                             (unsigned long long)(0xFFFFFFFFu - fl);
                    unsigned p = atomicAdd(&s_m, 1u);
                    if (p < SCAP) cand[p] = key;
                    else if (p < GCAP) g_keys[p] = key;
                    lvmax = max(lvmax, vb);
                }
            }
        }
#pragma unroll
        for (int o = 16; o; o >>= 1)
            lvmax = max(lvmax, __shfl_xor_sync(0xffffffffu, lvmax, o));
        if (lane == 0) atomicMax(&s_vmax, lvmax);
    }
    __syncthreads();  // bar7
    unsigned M = s_m;
    if (M > (unsigned)GCAP) M = (unsigned)GCAP;
    unsigned vmax = s_vmax;

    // ---- select-2: one-pass log-linear histogram on d = vmax - vb ----
    for (unsigned c = tid; c < M; c += 1024) {
        unsigned vb = (unsigned)(((c < SCAP) ? cand[c] : g_keys[c]) >> 32);
        atomicAdd(&hist[logbin(vmax - vb)], 1u);
    }
    __syncthreads();  // bar8
    if (wid == 0) BIN_FIND_ASC(k);   // if M < k, preset NBIN-1 stands (gather all)
    __syncthreads();  // bar9
    unsigned vlow;
    {
        unsigned long long dmax = binlow(s_kbin + 1) - 1ull;
        vlow = (dmax >= (unsigned long long)vmax) ? 0u : vmax - (unsigned)dmax;
    }

    // ---- gather all candidates with value-bits >= vlow (superset of top-k) ----
    for (unsigned c = tid; c < M; c += 1024) {
        unsigned long long key = (c < SCAP) ? cand[c] : g_keys[c];
        if ((unsigned)(key >> 32) >= vlow) {
            int p = atomicAdd(&s_cnt, 1);
            if (p < GATH) stop[p] = key;
        }
    }
    __syncthreads();  // bar10
    int n = s_cnt;
    if (n > GATH) n = GATH;

    // ---- exact rank sort over gathered keys (value desc, flat idx asc) ----
    float denom = s_denom;
    if (tid < n) {
        unsigned long long mykey = stop[tid];
        int rank = 0;
        for (int u = 0; u < n; u++) rank += (stop[u] > mykey);
        if (rank < k) {
            unsigned fl = 0xFFFFFFFFu - (unsigned)(mykey & 0xFFFFFFFFull);
            unsigned ii = fl / NN, jj = fl % NN;
            float v = __uint_as_float((unsigned)(mykey >> 32));
            if (2 * rank + 1 < out_size) {
                out[2 * rank] = (float)ii;
                out[2 * rank + 1] = (float)jj;
            }
            if (2 * k + rank < out_size) out[2 * k + rank] = v / denom;
        }
    }
    for (int c = 3 * k + tid; c < out_size; c += 1024) out[c] = 0.f;
}

extern "C" void kernel_launch(void* const* d_in, const int* in_sizes, int n_in,
                              void* d_out, int out_size) {
    const float* G = (const float*)d_in[0];
    const float* wb = (const float*)d_in[1];
    const float* we = (const float*)d_in[2];
    const int* kp = (const int*)d_in[3];
    float* out = (float*)d_out;

    k_dots<<<NBD, 1024>>>(G, wb, we);
    k_master<<<1, 1024>>>(kp, out, out_size);
}

// round 11
// speedup vs baseline: 2.8401x; 1.0173x over previous
#include <cuda_runtime.h>
#include <math.h>

#define NN 8192
#define DDIM 200
#define NBD 128
#define GCAP (1 << 18)
#define SCAP 3072
#define JCAP 1024
#define RCAP 256
#define GATH 512
#define NBIN 896
#define KMAX 128

__device__ float g_b[NN], g_e[NN];
__device__ float g_pb[NBD], g_pe[NBD];
__device__ int g_Ri[NN];
__device__ float g_Rb[NN];
__device__ int g_Jj[NN];
__device__ float g_Je[NN];
__device__ unsigned long long g_keys[GCAP];

__device__ __forceinline__ float dot4(float4 a, float4 w, float acc) {
    return fmaf(a.x, w.x, fmaf(a.y, w.y, fmaf(a.z, w.z, fmaf(a.w, w.w, acc))));
}

// ---------- GEMV: 128 blocks (single wave), 2 rows/warp, front-batched loads ----------
__global__ void __launch_bounds__(1024) k_dots(const float* __restrict__ G,
                                               const float* __restrict__ wb,
                                               const float* __restrict__ we) {
    int wid = threadIdx.x >> 5;
    int lane = threadIdx.x & 31;
    int row0 = blockIdx.x * 64 + wid * 2;
    const float4* r0 = reinterpret_cast<const float4*>(G + (size_t)row0 * DDIM);
    const float4* r1 = reinterpret_cast<const float4*>(G + (size_t)(row0 + 1) * DDIM);
    const float4* wb4 = reinterpret_cast<const float4*>(wb);
    const float4* we4 = reinterpret_cast<const float4*>(we);
    bool hasB = (lane + 32) < (DDIM / 4);
    int qb = hasB ? lane + 32 : lane;
    // front-batch all independent loads for MLP
    float4 a0 = r0[lane];
    float4 a1 = r1[lane];
    float4 a0B = r0[qb];
    float4 a1B = r1[qb];
    float4 wA = __ldg(&wb4[lane]);
    float4 eA = __ldg(&we4[lane]);
    float4 wB = __ldg(&wb4[qb]);
    float4 eB = __ldg(&we4[qb]);
    float sb0 = dot4(a0, wA, 0.f), se0 = dot4(a0, eA, 0.f);
    float sb1 = dot4(a1, wA, 0.f), se1 = dot4(a1, eA, 0.f);
    if (hasB) {
        sb0 = dot4(a0B, wB, sb0); se0 = dot4(a0B, eB, se0);
        sb1 = dot4(a1B, wB, sb1); se1 = dot4(a1B, eB, se1);
    }
#pragma unroll
    for (int o = 16; o; o >>= 1) {
        sb0 += __shfl_xor_sync(0xffffffffu, sb0, o);
        se0 += __shfl_xor_sync(0xffffffffu, se0, o);
        sb1 += __shfl_xor_sync(0xffffffffu, sb1, o);
        se1 += __shfl_xor_sync(0xffffffffu, se1, o);
    }
    __shared__ float eb[32], ee[32];
    if (lane == 0) {
        g_b[row0] = sb0;
        g_b[row0 + 1] = sb1;
        g_e[row0] = se0;
        g_e[row0 + 1] = se1;
        eb[wid] = expf(sb0) + expf(sb1);
        ee[wid] = expf(se0) + expf(se1);
    }
    __syncthreads();
    if (wid == 0) {
        float v = eb[lane];
#pragma unroll
        for (int o = 16; o; o >>= 1) v += __shfl_down_sync(0xffffffffu, v, o);
        if (lane == 0) g_pb[blockIdx.x] = v;
    } else if (wid == 1) {
        float v = ee[lane];
#pragma unroll
        for (int o = 16; o; o >>= 1) v += __shfl_down_sync(0xffffffffu, v, o);
        if (lane == 0) g_pe[blockIdx.x] = v;
    }
}

__device__ __forceinline__ unsigned f2u(float x) {
    unsigned u = __float_as_uint(x);
    return (u & 0x80000000u) ? ~u : (u | 0x80000000u);
}
__device__ __forceinline__ float u2f(unsigned u) {
    unsigned v = (u & 0x80000000u) ? (u & 0x7FFFFFFFu) : ~u;
    return __uint_as_float(v);
}

// log-linear bin of distance d (monotone non-decreasing), bins [0, NBIN)
__device__ __forceinline__ int logbin(unsigned d) {
    if (d < 32u) return (int)d;
    int m = 31 - __clz(d);
    return ((m - 5) << 5) + (int)((d >> (m - 5)) & 31u) + 32;
}
// smallest d with logbin(d) == b  (64-bit to handle b == NBIN)
__device__ __forceinline__ unsigned long long binlow(int b) {
    if (b < 32) return (unsigned long long)b;
    int m = 5 + ((b - 32) >> 5);
    int sub = (b - 32) & 31;
    return (unsigned long long)(32 + sub) << (m - 5);
}

// one-warp ascending bin-find over dual-plane hist: smallest bin with cum >= k_in
#define BIN_FIND_ASC(k_in)                                                       \
    do {                                                                         \
        int lsum = 0;                                                            \
        int hb = tid * (NBIN / 32);                                              \
        _Pragma("unroll") for (int t = 0; t < NBIN / 32; t++)                    \
            lsum += (int)hist[hb + t] + (int)hist[NBIN + hb + t];                \
        int pre = lsum;                                                          \
        _Pragma("unroll") for (int o = 1; o < 32; o <<= 1) {                     \
            int u = __shfl_up_sync(0xffffffffu, pre, o);                         \
            if (tid >= o) pre += u;                                              \
        }                                                                        \
        int runc = pre - lsum;                                                   \
        for (int t = 0; t < NBIN / 32; t++) {                                    \
            int h = (int)hist[hb + t] + (int)hist[NBIN + hb + t];                \
            if (runc < (k_in) && runc + h >= (k_in)) s_kbin = hb + t;            \
            runc += h;                                                           \
        }                                                                        \
    } while (0)

__global__ void __launch_bounds__(1024) k_master(const int* __restrict__ kp,
                                                 float* __restrict__ out,
                                                 int out_size) {
    __shared__ __align__(16) unsigned long long cand[SCAP];   // 24KB
    __shared__ __align__(16) unsigned hist[2 * NBIN];         // 7KB (dual plane)
    __shared__ int sjidx[JCAP];
    __shared__ float sje[JCAP];                               // 8KB
    __shared__ int sri[RCAP];
    __shared__ float srb[RCAP];                               // 2KB
    __shared__ unsigned long long stop[GATH];                 // 4KB
    __shared__ float wtot[32], wexcl[32];
    __shared__ float sda[8], sdb[8];
    __shared__ float s_denom;
    __shared__ unsigned s_umax, s_vmax, s_emax;
    __shared__ int s_kbin;
    __shared__ int s_nR, s_nJ, s_cnt;
    __shared__ unsigned s_m;

    int tid = threadIdx.x;
    int lane = tid & 31;
    int wid = tid >> 5;
    int plane = (wid & 1) * NBIN;
    int k = *kp;
    if (k < 1) k = 1;
    if (k > KMAX) k = KMAX;
    int base = tid * 8;

    // ---- load working set into registers (vectorized) ----
    float bi[8], el[8], cl[8];
    {
        const float4* bp = reinterpret_cast<const float4*>(g_b) + tid * 2;
        const float4* ep = reinterpret_cast<const float4*>(g_e) + tid * 2;
        float4 b0 = bp[0], b1 = bp[1], e0 = ep[0], e1 = ep[1];
        bi[0] = b0.x; bi[1] = b0.y; bi[2] = b0.z; bi[3] = b0.w;
        bi[4] = b1.x; bi[5] = b1.y; bi[6] = b1.z; bi[7] = b1.w;
        el[0] = e0.x; el[1] = e0.y; el[2] = e0.z; el[3] = e0.w;
        el[4] = e1.x; el[5] = e1.y; el[6] = e1.z; el[7] = e1.w;
    }

    // local prefix-max(b) partials + e-max
    float lex;
    {
        float run = -INFINITY;
#pragma unroll
        for (int t = 0; t < 8; t++) { run = fmaxf(run, bi[t]); cl[t] = run; }
        float incl = run;
#pragma unroll
        for (int o = 1; o < 32; o <<= 1) {
            float u = __shfl_up_sync(0xffffffffu, incl, o);
            if (lane >= o) incl = fmaxf(incl, u);
        }
        if (lane == 31) wtot[wid] = incl;
        lex = __shfl_up_sync(0xffffffffu, incl, 1);
        if (lane == 0) lex = -INFINITY;
    }
    // denominator partial reduce (float)
    if (wid < 8) {
        float dv = (tid < 128) ? g_pb[tid] : g_pe[tid - 128];
#pragma unroll
        for (int o = 16; o; o >>= 1) dv += __shfl_down_sync(0xffffffffu, dv, o);
        if (lane == 0) { if (wid < 4) sda[wid] = dv; else sdb[wid - 4] = dv; }
    }
    // hist clear + scalar init
    if (tid >= 512 && tid < 512 + 2 * NBIN / 4) {
        int h4 = (tid - 512) * 4;
        *reinterpret_cast<uint4*>(&hist[h4]) = make_uint4(0u, 0u, 0u, 0u);
    }
    if (tid == 0) {
        s_nR = 0; s_nJ = 0; s_m = 0; s_cnt = 0;
        s_umax = 0u; s_vmax = 0u; s_emax = 0u; s_kbin = NBIN - 1;
    }
    // e-max (global, for R pruning)
    {
        unsigned lem = 0u;
#pragma unroll
        for (int t = 0; t < 8; t++) lem = max(lem, f2u(el[t]));
#pragma unroll
        for (int o = 16; o; o >>= 1)
            lem = max(lem, __shfl_xor_sync(0xffffffffu, lem, o));
        if (lane == 0) atomicMax(&s_emax, lem);
    }
    __syncthreads();  // bar1

    if (wid == 0) {
        float incl = wtot[lane];
#pragma unroll
        for (int o = 1; o < 32; o <<= 1) {
            float u = __shfl_up_sync(0xffffffffu, incl, o);
            if (lane >= o) incl = fmaxf(incl, u);
        }
        float ex = __shfl_up_sync(0xffffffffu, incl, 1);
        if (lane == 0) ex = -INFINITY;
        wexcl[lane] = ex;
    } else if (tid == 32) {
        float a = sda[0] + sda[1] + sda[2] + sda[3];
        float b2 = sdb[0] + sdb[1] + sdb[2] + sdb[3];
        s_denom = a * b2;
    }
    __syncthreads();  // bar2

    // finalize c_j; per-warp c max -> shared atomic
    {
        float exP = fmaxf(wexcl[wid], lex);
        unsigned lmax = 0u;
#pragma unroll
        for (int t = 0; t < 8; t++) {
            cl[t] = fmaxf(cl[t], exP) + el[t];
            lmax = max(lmax, f2u(cl[t]));
        }
#pragma unroll
        for (int o = 16; o; o >>= 1)
            lmax = max(lmax, __shfl_xor_sync(0xffffffffu, lmax, o));
        if (lane == 0) atomicMax(&s_umax, lmax);
    }
    __syncthreads();  // bar3

    // ---- select-1: one-pass log-linear histogram on d = umax - f2u(c) ----
    unsigned umax = s_umax;
    float maxE = u2f(s_emax);
#pragma unroll
    for (int t = 0; t < 8; t++)
        atomicAdd(&hist[plane + logbin(umax - f2u(cl[t]))], 1u);
    __syncthreads();  // bar4
    if (wid == 0) BIN_FIND_ASC(k);
    __syncthreads();  // bar5
    // exact threshold: u >= ulow  <=>  logbin(umax-u) <= kbin
    unsigned ulow;
    {
        unsigned long long dmax = binlow(s_kbin + 1) - 1ull;
        ulow = (dmax >= (unsigned long long)umax) ? 0u : umax - (unsigned)dmax;
    }
    float T = u2f(ulow);

    // ---- build J and R lists; clear hist; reset kbin ----
#pragma unroll
    for (int t = 0; t < 8; t++) {
        if (f2u(cl[t]) >= ulow) {
            int p = atomicAdd(&s_nJ, 1);
            if (p < JCAP) { sjidx[p] = base + t; sje[p] = el[t]; }
            else { g_Jj[p] = base + t; g_Je[p] = el[t]; }
        }
    }
#pragma unroll
    for (int t = 0; t < 8; t++) {
        if (bi[t] + maxE >= T) {   // global-max prune: superset of suffix-max prune
            int p = atomicAdd(&s_nR, 1);
            if (p < RCAP) { sri[p] = base + t; srb[p] = bi[t]; }
            else { g_Ri[p] = base + t; g_Rb[p] = bi[t]; }
        }
    }
    if (tid >= 512 && tid < 512 + 2 * NBIN / 4) {   // clear AFTER binfind consumed
        int h4 = (tid - 512) * 4;
        *reinterpret_cast<uint4*>(&hist[h4]) = make_uint4(0u, 0u, 0u, 0u);
    }
    __syncthreads();  // bar6

    // ---- enumerate R x J (warp per row); track value-bit max ----
    if (tid == 0) s_kbin = NBIN - 1;   // consumed before bar6, re-read after bar9
    {
        int nR = s_nR, nJ = s_nJ;
        unsigned lvmax = 0u;
        for (int r = wid; r < nR; r += 32) {
            int i = (r < RCAP) ? sri[r] : g_Ri[r];
            float bv = (r < RCAP) ? srb[r] : g_Rb[r];
            for (int q = lane; q < nJ; q += 32) {
                int j;
                float ej;
                if (q < JCAP) { j = sjidx[q]; ej = sje[q]; }
                else { j = g_Jj[q]; ej = g_Je[q]; }
                float s = bv + ej;
                if (j >= i && s >= T) {   // exact superset condition (same fl as keys)
                    float v = expf(s);
                    unsigned vb = __float_as_uint(v);
                    unsigned fl = (unsigned)i * NN + (unsigned)j;
                    unsigned long long key = ((unsigned long long)vb << 32) |
                                             (unsigned long long)(0xFFFFFFFFu - fl);
                    unsigned p = atomicAdd(&s_m, 1u);
                    if (p < SCAP) cand[p] = key;
                    else if (p < GCAP) g_keys[p] = key;
                    lvmax = max(lvmax, vb);
                }
            }
        }
#pragma unroll
        for (int o = 16; o; o >>= 1)
            lvmax = max(lvmax, __shfl_xor_sync(0xffffffffu, lvmax, o));
        if (lane == 0) atomicMax(&s_vmax, lvmax);
    }
    __syncthreads();  // bar7
    unsigned M = s_m;
    if (M > (unsigned)GCAP) M = (unsigned)GCAP;
    unsigned vmax = s_vmax;

    // ---- select-2: one-pass log-linear histogram on d = vmax - vb ----
    for (unsigned c = tid; c < M; c += 1024) {
        unsigned vb = (unsigned)(((c < SCAP) ? cand[c] : g_keys[c]) >> 32);
        atomicAdd(&hist[plane + logbin(vmax - vb)], 1u);
    }
    __syncthreads();  // bar8
    if (wid == 0) BIN_FIND_ASC(k);   // if M < k, preset NBIN-1 stands (gather all)
    __syncthreads();  // bar9
    unsigned vlow;
    {
        unsigned long long dmax = binlow(s_kbin + 1) - 1ull;
        vlow = (dmax >= (unsigned long long)vmax) ? 0u : vmax - (unsigned)dmax;
    }

    // ---- gather all candidates with value-bits >= vlow (superset of top-k) ----
    for (unsigned c = tid; c < M; c += 1024) {
        unsigned long long key = (c < SCAP) ? cand[c] : g_keys[c];
        if ((unsigned)(key >> 32) >= vlow) {
            int p = atomicAdd(&s_cnt, 1);
            if (p < GATH) stop[p] = key;
        }
    }
    __syncthreads();  // bar10
    int n = s_cnt;
    if (n > GATH) n = GATH;

    // ---- exact rank sort over gathered keys (value desc, flat idx asc) ----
    float denom = s_denom;
    if (tid < n) {
        unsigned long long mykey = stop[tid];
        int rank = 0;
        for (int u = 0; u < n; u++) rank += (stop[u] > mykey);
        if (rank < k) {
            unsigned fl = 0xFFFFFFFFu - (unsigned)(mykey & 0xFFFFFFFFull);
            unsigned ii = fl / NN, jj = fl % NN;
            float v = __uint_as_float((unsigned)(mykey >> 32));
            if (2 * rank + 1 < out_size) {
                out[2 * rank] = (float)ii;
                out[2 * rank + 1] = (float)jj;
            }
            if (2 * k + rank < out_size) out[2 * k + rank] = v / denom;
        }
    }
    for (int c = 3 * k + tid; c < out_size; c += 1024) out[c] = 0.f;
}

extern "C" void kernel_launch(void* const* d_in, const int* in_sizes, int n_in,
                              void* d_out, int out_size) {
    const float* G = (const float*)d_in[0];
    const float* wb = (const float*)d_in[1];
    const float* we = (const float*)d_in[2];
    const int* kp = (const int*)d_in[3];
    float* out = (float*)d_out;

    k_dots<<<NBD, 1024>>>(G, wb, we);
    k_master<<<1, 1024>>>(kp, out, out_size);
}